// round 1
// baseline (speedup 1.0000x reference)
#include <cuda_runtime.h>
#include <math.h>

#define DIMC 1024
#define NH 16
#define HD 64
#define BATCH 4
#define SEQ 2048
#define BT (BATCH*SEQ)

// Scratch (allocation-free): q/k/v in [B,H,T,D], attention out in [B,T,C]
__device__ float g_q[(size_t)BATCH*NH*SEQ*HD];
__device__ float g_k[(size_t)BATCH*NH*SEQ*HD];
__device__ float g_v[(size_t)BATCH*NH*SEQ*HD];
__device__ float g_att[(size_t)BT*DIMC];

// ---------------------------------------------------------------------------
// GEMM: C[M,N] = A[M,K] * W[K,N] + bias ; M=8192, N=K=1024
// 64x64 block tile, BK=16, 256 threads, 4x4 per thread, fp32 FFMA.
// DOROPE: apply rotary in epilogue. DEST: 0=g_q 1=g_k 2=g_v 3=outp.
// ASRC: 1 -> read A from g_att symbol (final projection).
// ---------------------------------------------------------------------------
template<int DOROPE, int DEST, int ASRC>
__global__ __launch_bounds__(256) void gemm_kernel(const float* __restrict__ A,
                                                   const float* __restrict__ W,
                                                   const float* __restrict__ bias,
                                                   float* __restrict__ outp)
{
    __shared__ __align__(16) float As[16][64];   // [k][m]
    __shared__ __align__(16) float Bs[16][64];   // [k][n]

    const float* Ap = ASRC ? (const float*)g_att : A;
    float* out = (DEST == 0) ? g_q : (DEST == 1) ? g_k : (DEST == 2) ? g_v : outp;

    int tid = threadIdx.x;
    int tx = tid & 15, ty = tid >> 4;
    int m0 = blockIdx.y << 6;
    int n0 = blockIdx.x << 6;

    float acc[4][4];
    #pragma unroll
    for (int i = 0; i < 4; i++)
        #pragma unroll
        for (int j = 0; j < 4; j++) acc[i][j] = 0.f;

    for (int k0 = 0; k0 < DIMC; k0 += 16) {
        // A tile: 64 rows x 16 k ; each thread one float4 from one row
        {
            int row = tid >> 2, kg = (tid & 3) << 2;
            float4 a = *(const float4*)&Ap[(size_t)(m0 + row) * DIMC + k0 + kg];
            As[kg + 0][row] = a.x; As[kg + 1][row] = a.y;
            As[kg + 2][row] = a.z; As[kg + 3][row] = a.w;
        }
        // W tile: 16 k-rows x 64 n
        {
            int kr = tid >> 4, cg = (tid & 15) << 2;
            *(float4*)&Bs[kr][cg] = *(const float4*)&W[(size_t)(k0 + kr) * DIMC + n0 + cg];
        }
        __syncthreads();
        #pragma unroll
        for (int kk = 0; kk < 16; kk++) {
            float4 av = *(const float4*)&As[kk][ty << 2];
            float4 bv = *(const float4*)&Bs[kk][tx << 2];
            float aa[4] = {av.x, av.y, av.z, av.w};
            float bb[4] = {bv.x, bv.y, bv.z, bv.w};
            #pragma unroll
            for (int i = 0; i < 4; i++)
                #pragma unroll
                for (int j = 0; j < 4; j++) acc[i][j] += aa[i] * bb[j];
        }
        __syncthreads();
    }

    int gn_base = n0 + (tx << 2);
    #pragma unroll
    for (int i = 0; i < 4; i++) {
        int gm = m0 + (ty << 2) + i;
        if (DEST <= 2) {
            int b = gm >> 11;        // / SEQ
            int t = gm & (SEQ - 1);
            #pragma unroll
            for (int p = 0; p < 2; p++) {
                int ne = gn_base + 2 * p;
                float xe = acc[i][2 * p]     + bias[ne];
                float xo = acc[i][2 * p + 1] + bias[ne + 1];
                int h = ne >> 6;
                int d = ne & 63;
                float oe, oo;
                if (DOROPE) {
                    // double-precision transcendentals: immune to fast-math
                    float invf = (float)(1.0 / pow(10000.0, (double)d / 64.0));
                    float ang  = (float)t * invf;       // fp32 mult matches np.outer
                    float cs = (float)cos((double)ang);
                    float sn = (float)sin((double)ang);
                    oe = xe * cs - xo * sn;
                    oo = xe * sn + xo * cs;
                } else { oe = xe; oo = xo; }
                size_t base = ((size_t)(b * NH + h) * SEQ + t) * HD + d;
                out[base]     = oe;
                out[base + 1] = oo;
            }
        } else {
            #pragma unroll
            for (int j = 0; j < 4; j++)
                out[(size_t)gm * DIMC + gn_base + j] = acc[i][j] + bias[gn_base + j];
        }
    }
}

// ---------------------------------------------------------------------------
// Causal flash attention, fp32. Block: 64 query rows x D=64, 256 threads.
// Tiles of 64 keys; online softmax. smem: qs(Qt) + kps(Kt then Pt) + vs = 48KB.
// ---------------------------------------------------------------------------
__global__ __launch_bounds__(256) void attn_kernel()
{
    __shared__ __align__(16) float qs [64][64];  // [d][row]
    __shared__ __align__(16) float kps[64][64];  // K: [d][col]  then  P: [col][row]
    __shared__ __align__(16) float vs [64][64];  // [srow][dim]

    int tid = threadIdx.x;
    int tx = tid & 15, ty = tid >> 4;
    int m0 = blockIdx.x << 6;
    int bh = blockIdx.y;

    const float* Qb = g_q + (size_t)bh * SEQ * HD;
    const float* Kb = g_k + (size_t)bh * SEQ * HD;
    const float* Vb = g_v + (size_t)bh * SEQ * HD;

    // load Q tile transposed
    #pragma unroll
    for (int c = 0; c < 4; c++) {
        int f4 = tid + c * 256;
        int row = f4 >> 4, dg = (f4 & 15) << 2;
        float4 q = *(const float4*)&Qb[(size_t)(m0 + row) * HD + dg];
        qs[dg + 0][row] = q.x; qs[dg + 1][row] = q.y;
        qs[dg + 2][row] = q.z; qs[dg + 3][row] = q.w;
    }

    float o[4][4];
    float mrow[4], lrow[4];
    #pragma unroll
    for (int i = 0; i < 4; i++) {
        mrow[i] = -1e30f; lrow[i] = 0.f;
        #pragma unroll
        for (int j = 0; j < 4; j++) o[i][j] = 0.f;
    }

    for (int s0 = 0; s0 <= m0; s0 += 64) {
        __syncthreads();   // previous P*V reads done before overwriting kps/vs
        #pragma unroll
        for (int c = 0; c < 4; c++) {
            int f4 = tid + c * 256;
            int row = f4 >> 4, dg = (f4 & 15) << 2;
            float4 kq = *(const float4*)&Kb[(size_t)(s0 + row) * HD + dg];
            kps[dg + 0][row] = kq.x; kps[dg + 1][row] = kq.y;
            kps[dg + 2][row] = kq.z; kps[dg + 3][row] = kq.w;
            *(float4*)&vs[row][dg] = *(const float4*)&Vb[(size_t)(s0 + row) * HD + dg];
        }
        __syncthreads();

        // S = Q K^T  (4x4 per thread)
        float s[4][4];
        #pragma unroll
        for (int i = 0; i < 4; i++)
            #pragma unroll
            for (int j = 0; j < 4; j++) s[i][j] = 0.f;

        #pragma unroll 16
        for (int kd = 0; kd < 64; kd++) {
            float4 qv = *(const float4*)&qs [kd][ty << 2];
            float4 kv = *(const float4*)&kps[kd][tx << 2];
            float aa[4] = {qv.x, qv.y, qv.z, qv.w};
            float bb[4] = {kv.x, kv.y, kv.z, kv.w};
            #pragma unroll
            for (int i = 0; i < 4; i++)
                #pragma unroll
                for (int j = 0; j < 4; j++) s[i][j] += aa[i] * bb[j];
        }

        const float scale = 0.125f;   // 1/sqrt(64)
        bool diag = (s0 == m0);
        #pragma unroll
        for (int i = 0; i < 4; i++) {
            #pragma unroll
            for (int j = 0; j < 4; j++) {
                s[i][j] *= scale;
                if (diag && (s0 + (tx << 2) + j) > (m0 + (ty << 2) + i))
                    s[i][j] = -1e30f;
            }
        }

        // online softmax per row (reduce across 16 lanes sharing ty)
        #pragma unroll
        for (int i = 0; i < 4; i++) {
            float mx = fmaxf(fmaxf(s[i][0], s[i][1]), fmaxf(s[i][2], s[i][3]));
            mx = fmaxf(mx, __shfl_xor_sync(0xffffffffu, mx, 1, 16));
            mx = fmaxf(mx, __shfl_xor_sync(0xffffffffu, mx, 2, 16));
            mx = fmaxf(mx, __shfl_xor_sync(0xffffffffu, mx, 4, 16));
            mx = fmaxf(mx, __shfl_xor_sync(0xffffffffu, mx, 8, 16));
            float mnew = fmaxf(mrow[i], mx);
            float corr = expf(mrow[i] - mnew);
            float su = 0.f;
            #pragma unroll
            for (int j = 0; j < 4; j++) { s[i][j] = expf(s[i][j] - mnew); su += s[i][j]; }
            su += __shfl_xor_sync(0xffffffffu, su, 1, 16);
            su += __shfl_xor_sync(0xffffffffu, su, 2, 16);
            su += __shfl_xor_sync(0xffffffffu, su, 4, 16);
            su += __shfl_xor_sync(0xffffffffu, su, 8, 16);
            lrow[i] = lrow[i] * corr + su;
            mrow[i] = mnew;
            #pragma unroll
            for (int j = 0; j < 4; j++) o[i][j] *= corr;
        }

        __syncthreads();   // scores done reading kps (K) before P overwrite
        #pragma unroll
        for (int i = 0; i < 4; i++)
            #pragma unroll
            for (int j = 0; j < 4; j++)
                kps[(tx << 2) + j][(ty << 2) + i] = s[i][j];   // P^T: [col][row]
        __syncthreads();

        // O += P V
        #pragma unroll 16
        for (int j = 0; j < 64; j++) {
            float4 pv = *(const float4*)&kps[j][ty << 2];
            float4 vv = *(const float4*)&vs [j][tx << 2];
            float aa[4] = {pv.x, pv.y, pv.z, pv.w};
            float bb[4] = {vv.x, vv.y, vv.z, vv.w};
            #pragma unroll
            for (int i = 0; i < 4; i++)
                #pragma unroll
                for (int c = 0; c < 4; c++) o[i][c] += aa[i] * bb[c];
        }
    }

    int b = bh >> 4, h = bh & 15;
    #pragma unroll
    for (int i = 0; i < 4; i++) {
        float inv = 1.0f / lrow[i];
        int trow = m0 + (ty << 2) + i;
        size_t base = ((size_t)(b * SEQ + trow)) * DIMC + h * HD + (tx << 2);
        #pragma unroll
        for (int j = 0; j < 4; j++) g_att[base + j] = o[i][j] * inv;
    }
}

extern "C" void kernel_launch(void* const* d_in, const int* in_sizes, int n_in,
                              void* d_out, int out_size)
{
    const float* query = (const float*)d_in[0];
    const float* key   = (const float*)d_in[1];
    const float* value = (const float*)d_in[2];
    const float* Wq = (const float*)d_in[3];
    const float* bq = (const float*)d_in[4];
    const float* Wk = (const float*)d_in[5];
    const float* bk = (const float*)d_in[6];
    const float* Wv = (const float*)d_in[7];
    const float* bv = (const float*)d_in[8];
    const float* Wo = (const float*)d_in[9];
    const float* bo = (const float*)d_in[10];
    float* out = (float*)d_out;

    dim3 gg(DIMC / 64, BT / 64);   // (16, 128)
    dim3 gb(256);

    gemm_kernel<1, 0, 0><<<gg, gb>>>(query, Wq, bq, nullptr);   // Q proj + RoPE
    gemm_kernel<1, 1, 0><<<gg, gb>>>(key,   Wk, bk, nullptr);   // K proj + RoPE
    gemm_kernel<0, 2, 0><<<gg, gb>>>(value, Wv, bv, nullptr);   // V proj

    attn_kernel<<<dim3(SEQ / 64, BATCH * NH), 256>>>();         // causal flash attn

    gemm_kernel<0, 3, 1><<<gg, gb>>>(nullptr, Wo, bo, out);     // output proj
}

// round 5
// speedup vs baseline: 1.6330x; 1.6330x over previous
#include <cuda_runtime.h>
#include <cuda_bf16.h>
#include <math.h>
#include <stdint.h>

#define DIMC 1024
#define NH 16
#define HD 64
#define BATCH 4
#define SEQ 2048
#define BT (BATCH*SEQ)

// ---------------- scratch (allocation-free) ----------------
__device__ float g_q[(size_t)BATCH*NH*SEQ*HD];
__device__ float g_k[(size_t)BATCH*NH*SEQ*HD];
__device__ float g_v[(size_t)BATCH*NH*SEQ*HD];
__device__ float g_att[(size_t)BT*DIMC];
__device__ __nv_bfloat16 g_ahi[(size_t)BT*DIMC];
__device__ __nv_bfloat16 g_alo[(size_t)BT*DIMC];
__device__ __nv_bfloat16 g_whi[(size_t)DIMC*DIMC];   // [N,K]
__device__ __nv_bfloat16 g_wlo[(size_t)DIMC*DIMC];   // [N,K]
__device__ float2 g_rope[SEQ*32];                    // (cos,sin) per (t, d/2)

// ---------------- mma.sync helper (sm_80+ PTX, compute_103-safe) ----------------
__device__ __forceinline__ void mma16816(float* d, const uint32_t* a, uint32_t b0, uint32_t b1) {
    asm volatile("mma.sync.aligned.m16n8k16.row.col.f32.bf16.bf16.f32 "
                 "{%0,%1,%2,%3}, {%4,%5,%6,%7}, {%8,%9}, {%0,%1,%2,%3};"
                 : "+f"(d[0]), "+f"(d[1]), "+f"(d[2]), "+f"(d[3])
                 : "r"(a[0]), "r"(a[1]), "r"(a[2]), "r"(a[3]), "r"(b0), "r"(b1));
}

// ---------------- helper kernels ----------------
__global__ __launch_bounds__(256) void rope_table_kernel() {
    int idx = blockIdx.x * 256 + threadIdx.x;        // 65536 = 2048*32
    int t = idx >> 5, f = idx & 31;
    double invf = 1.0 / pow(10000.0, (double)(2 * f) / 64.0);
    float ang = (float)t * (float)invf;
    g_rope[idx] = make_float2((float)cos((double)ang), (float)sin((double)ang));
}

// elementwise fp32 -> (hi,lo) bf16 split, A stays [M,K] row-major
// FROMATT=1: read from device symbol g_att (device-side resolution — a __device__
// symbol must NEVER be passed as a host-side kernel argument).
template<int FROMATT>
__global__ __launch_bounds__(256) void asplit_kernel(const float4* __restrict__ in) {
    const float4* src = FROMATT ? (const float4*)g_att : in;
    int i = blockIdx.x * 256 + threadIdx.x;           // n4 = BT*DIMC/4
    float4 v = src[i];
    float vv[4] = {v.x, v.y, v.z, v.w};
    __nv_bfloat16 h[4], l[4];
    #pragma unroll
    for (int j = 0; j < 4; j++) {
        h[j] = __float2bfloat16(vv[j]);
        l[j] = __float2bfloat16(vv[j] - __bfloat162float(h[j]));
    }
    *(uint2*)(g_ahi + 4 * (size_t)i) = *(uint2*)h;
    *(uint2*)(g_alo + 4 * (size_t)i) = *(uint2*)l;
}

// W [K,N] fp32 -> transposed (hi,lo) bf16 [N,K]
__global__ __launch_bounds__(256) void wsplit_kernel(const float* __restrict__ W) {
    __shared__ float tile[32][33];
    int n0 = blockIdx.x * 32, k0 = blockIdx.y * 32;
    int x = threadIdx.x, y0 = threadIdx.y;            // block (32,8)
    for (int j = y0; j < 32; j += 8)
        tile[j][x] = W[(size_t)(k0 + j) * DIMC + n0 + x];
    __syncthreads();
    for (int j = y0; j < 32; j += 8) {
        float v = tile[x][j];                         // = W[k0+x][n0+j]
        __nv_bfloat16 h = __float2bfloat16(v);
        size_t o = (size_t)(n0 + j) * DIMC + k0 + x;
        g_whi[o] = h;
        g_wlo[o] = __float2bfloat16(v - __bfloat162float(h));
    }
}

// ---------------- HMMA GEMM: C[8192,1024] = A W + b, 3-term bf16 split ----------------
// CTA 128x128, BK=32, 8 warps (warp tile 64x32).
// Fragments loaded with plain 32-bit LDS (no ldmatrix): smem viewed as uint32,
// row stride 20 u32 (= 32 halves data + 8 pad) -> quad-strided access conflict-free.
// DEST: 0=g_q(+RoPE) 1=g_k(+RoPE) 2=g_v 3=outp
#define S32 20   // uint32 stride per row

template<int DOROPE, int DEST>
__global__ __launch_bounds__(256) void hgemm_kernel(const float* __restrict__ bias,
                                                    float* __restrict__ outp)
{
    __shared__ __align__(16) uint32_t sAh[128 * S32];
    __shared__ __align__(16) uint32_t sAl[128 * S32];
    __shared__ __align__(16) uint32_t sBh[128 * S32];
    __shared__ __align__(16) uint32_t sBl[128 * S32];

    const int tid  = threadIdx.x;
    const int lane = tid & 31;
    const int wid  = tid >> 5;
    const int wm = wid & 1;          // 2 warp-rows of 64
    const int wn = wid >> 1;         // 4 warp-cols of 32
    const int m0 = blockIdx.y << 7, n0 = blockIdx.x << 7;

    float acc[4][4][4];
    #pragma unroll
    for (int i = 0; i < 4; i++)
        #pragma unroll
        for (int j = 0; j < 4; j++)
            #pragma unroll
            for (int r = 0; r < 4; r++) acc[i][j][r] = 0.f;

    const int qrow = lane >> 2;      // 0..7
    const int qk   = lane & 3;       // k-pair index 0..3

    for (int k0 = 0; k0 < DIMC; k0 += 32) {
        // ---- global -> smem: each thread 2 uint4 per array ----
        #pragma unroll
        for (int it = 0; it < 2; it++) {
            int i = tid + it * 256;              // 0..511
            int row = i >> 2, seg = i & 3;       // 128 rows x 4 segs of 8 halves
            size_t ga = (size_t)(m0 + row) * DIMC + k0 + seg * 8;
            size_t gb = (size_t)(n0 + row) * DIMC + k0 + seg * 8;
            int so = row * S32 + seg * 4;        // u32 offset, 16B aligned
            *(uint4*)(sAh + so) = *(const uint4*)(g_ahi + ga);
            *(uint4*)(sAl + so) = *(const uint4*)(g_alo + ga);
            *(uint4*)(sBh + so) = *(const uint4*)(g_whi + gb);
            *(uint4*)(sBl + so) = *(const uint4*)(g_wlo + gb);
        }
        __syncthreads();

        #pragma unroll
        for (int ks2 = 0; ks2 < 16; ks2 += 8) {   // k-halves 0-15 then 16-31 (u32 units)
            uint32_t ah[4][4], al[4][4], bh[4][2], bl[4][2];
            #pragma unroll
            for (int mt = 0; mt < 4; mt++) {
                int r0 = (wm * 64 + mt * 16 + qrow) * S32 + ks2 + qk;
                int r8 = r0 + 8 * S32;
                ah[mt][0] = sAh[r0];     ah[mt][1] = sAh[r8];
                ah[mt][2] = sAh[r0 + 4]; ah[mt][3] = sAh[r8 + 4];
                al[mt][0] = sAl[r0];     al[mt][1] = sAl[r8];
                al[mt][2] = sAl[r0 + 4]; al[mt][3] = sAl[r8 + 4];
            }
            #pragma unroll
            for (int nt = 0; nt < 4; nt++) {
                int nr = (wn * 32 + nt * 8 + qrow) * S32 + ks2 + qk;
                bh[nt][0] = sBh[nr]; bh[nt][1] = sBh[nr + 4];
                bl[nt][0] = sBl[nr]; bl[nt][1] = sBl[nr + 4];
            }
            #pragma unroll
            for (int mt = 0; mt < 4; mt++)
                #pragma unroll
                for (int nt = 0; nt < 4; nt++) {
                    mma16816(acc[mt][nt], ah[mt], bh[nt][0], bh[nt][1]);
                    mma16816(acc[mt][nt], ah[mt], bl[nt][0], bl[nt][1]);
                    mma16816(acc[mt][nt], al[mt], bh[nt][0], bh[nt][1]);
                }
        }
        __syncthreads();
    }

    const int quad = lane >> 2, tc = lane & 3;
    #pragma unroll
    for (int mt = 0; mt < 4; mt++) {
        #pragma unroll
        for (int nt = 0; nt < 4; nt++) {
            #pragma unroll
            for (int half = 0; half < 2; half++) {
                int m = m0 + wm * 64 + mt * 16 + quad + half * 8;
                int n = n0 + wn * 32 + nt * 8 + tc * 2;
                float v0 = acc[mt][nt][half * 2]     + bias[n];
                float v1 = acc[mt][nt][half * 2 + 1] + bias[n + 1];
                if (DEST <= 2) {
                    float* out = (DEST == 0) ? g_q : (DEST == 1) ? g_k : g_v;
                    int b = m >> 11, t = m & (SEQ - 1);
                    int h = n >> 6, d = n & 63;
                    float oe, oo;
                    if (DOROPE) {
                        float2 cs = g_rope[t * 32 + (d >> 1)];
                        oe = v0 * cs.x - v1 * cs.y;
                        oo = v0 * cs.y + v1 * cs.x;
                    } else { oe = v0; oo = v1; }
                    size_t base = ((size_t)(b * NH + h) * SEQ + t) * HD + d;
                    out[base]     = oe;
                    out[base + 1] = oo;
                } else {
                    size_t base = (size_t)m * DIMC + n;
                    outp[base]     = v0;
                    outp[base + 1] = v1;
                }
            }
        }
    }
}

// ---------------- causal flash attention, fp32 (unchanged, proven) ----------------
__global__ __launch_bounds__(256) void attn_kernel()
{
    __shared__ __align__(16) float qs [64][64];
    __shared__ __align__(16) float kps[64][64];
    __shared__ __align__(16) float vs [64][64];

    int tid = threadIdx.x;
    int tx = tid & 15, ty = tid >> 4;
    int m0 = blockIdx.x << 6;
    int bh = blockIdx.y;

    const float* Qb = g_q + (size_t)bh * SEQ * HD;
    const float* Kb = g_k + (size_t)bh * SEQ * HD;
    const float* Vb = g_v + (size_t)bh * SEQ * HD;

    #pragma unroll
    for (int c = 0; c < 4; c++) {
        int f4 = tid + c * 256;
        int row = f4 >> 4, dg = (f4 & 15) << 2;
        float4 q = *(const float4*)&Qb[(size_t)(m0 + row) * HD + dg];
        qs[dg + 0][row] = q.x; qs[dg + 1][row] = q.y;
        qs[dg + 2][row] = q.z; qs[dg + 3][row] = q.w;
    }

    float o[4][4];
    float mrow[4], lrow[4];
    #pragma unroll
    for (int i = 0; i < 4; i++) {
        mrow[i] = -1e30f; lrow[i] = 0.f;
        #pragma unroll
        for (int j = 0; j < 4; j++) o[i][j] = 0.f;
    }

    for (int s0 = 0; s0 <= m0; s0 += 64) {
        __syncthreads();
        #pragma unroll
        for (int c = 0; c < 4; c++) {
            int f4 = tid + c * 256;
            int row = f4 >> 4, dg = (f4 & 15) << 2;
            float4 kq = *(const float4*)&Kb[(size_t)(s0 + row) * HD + dg];
            kps[dg + 0][row] = kq.x; kps[dg + 1][row] = kq.y;
            kps[dg + 2][row] = kq.z; kps[dg + 3][row] = kq.w;
            *(float4*)&vs[row][dg] = *(const float4*)&Vb[(size_t)(s0 + row) * HD + dg];
        }
        __syncthreads();

        float s[4][4];
        #pragma unroll
        for (int i = 0; i < 4; i++)
            #pragma unroll
            for (int j = 0; j < 4; j++) s[i][j] = 0.f;

        #pragma unroll 16
        for (int kd = 0; kd < 64; kd++) {
            float4 qv = *(const float4*)&qs [kd][ty << 2];
            float4 kv = *(const float4*)&kps[kd][tx << 2];
            float aa[4] = {qv.x, qv.y, qv.z, qv.w};
            float bb[4] = {kv.x, kv.y, kv.z, kv.w};
            #pragma unroll
            for (int i = 0; i < 4; i++)
                #pragma unroll
                for (int j = 0; j < 4; j++) s[i][j] += aa[i] * bb[j];
        }

        const float scale = 0.125f;
        bool diag = (s0 == m0);
        #pragma unroll
        for (int i = 0; i < 4; i++) {
            #pragma unroll
            for (int j = 0; j < 4; j++) {
                s[i][j] *= scale;
                if (diag && (s0 + (tx << 2) + j) > (m0 + (ty << 2) + i))
                    s[i][j] = -1e30f;
            }
        }

        #pragma unroll
        for (int i = 0; i < 4; i++) {
            float mx = fmaxf(fmaxf(s[i][0], s[i][1]), fmaxf(s[i][2], s[i][3]));
            mx = fmaxf(mx, __shfl_xor_sync(0xffffffffu, mx, 1, 16));
            mx = fmaxf(mx, __shfl_xor_sync(0xffffffffu, mx, 2, 16));
            mx = fmaxf(mx, __shfl_xor_sync(0xffffffffu, mx, 4, 16));
            mx = fmaxf(mx, __shfl_xor_sync(0xffffffffu, mx, 8, 16));
            float mnew = fmaxf(mrow[i], mx);
            float corr = expf(mrow[i] - mnew);
            float su2 = 0.f;
            #pragma unroll
            for (int j = 0; j < 4; j++) { s[i][j] = expf(s[i][j] - mnew); su2 += s[i][j]; }
            su2 += __shfl_xor_sync(0xffffffffu, su2, 1, 16);
            su2 += __shfl_xor_sync(0xffffffffu, su2, 2, 16);
            su2 += __shfl_xor_sync(0xffffffffu, su2, 4, 16);
            su2 += __shfl_xor_sync(0xffffffffu, su2, 8, 16);
            lrow[i] = lrow[i] * corr + su2;
            mrow[i] = mnew;
            #pragma unroll
            for (int j = 0; j < 4; j++) o[i][j] *= corr;
        }

        __syncthreads();
        #pragma unroll
        for (int i = 0; i < 4; i++)
            #pragma unroll
            for (int j = 0; j < 4; j++)
                kps[(tx << 2) + j][(ty << 2) + i] = s[i][j];
        __syncthreads();

        #pragma unroll 16
        for (int j = 0; j < 64; j++) {
            float4 pv = *(const float4*)&kps[j][ty << 2];
            float4 vv = *(const float4*)&vs [j][tx << 2];
            float aa[4] = {pv.x, pv.y, pv.z, pv.w};
            float bb[4] = {vv.x, vv.y, vv.z, vv.w};
            #pragma unroll
            for (int i = 0; i < 4; i++)
                #pragma unroll
                for (int cc = 0; cc < 4; cc++) o[i][cc] += aa[i] * bb[cc];
        }
    }

    int b = bh >> 4, h = bh & 15;
    #pragma unroll
    for (int i = 0; i < 4; i++) {
        float inv = 1.0f / lrow[i];
        int trow = m0 + (ty << 2) + i;
        size_t base = ((size_t)(b * SEQ + trow)) * DIMC + h * HD + (tx << 2);
        #pragma unroll
        for (int j = 0; j < 4; j++) g_att[base + j] = o[i][j] * inv;
    }
}

// ---------------- launch ----------------
extern "C" void kernel_launch(void* const* d_in, const int* in_sizes, int n_in,
                              void* d_out, int out_size)
{
    const float* query = (const float*)d_in[0];
    const float* key   = (const float*)d_in[1];
    const float* value = (const float*)d_in[2];
    const float* Wq = (const float*)d_in[3];
    const float* bq = (const float*)d_in[4];
    const float* Wk = (const float*)d_in[5];
    const float* bk = (const float*)d_in[6];
    const float* Wv = (const float*)d_in[7];
    const float* bv = (const float*)d_in[8];
    const float* Wo = (const float*)d_in[9];
    const float* bo = (const float*)d_in[10];
    float* out = (float*)d_out;

    dim3 gg(DIMC / 128, BT / 128);   // (8, 64)
    dim3 gw(DIMC / 32, DIMC / 32);   // (32, 32)
    int n4 = BT * DIMC / 4;

    rope_table_kernel<<<SEQ * 32 / 256, 256>>>();

    asplit_kernel<0><<<n4 / 256, 256>>>((const float4*)query);
    wsplit_kernel<<<gw, dim3(32, 8)>>>(Wq);
    hgemm_kernel<1,0><<<gg, 256>>>(bq, nullptr);

    asplit_kernel<0><<<n4 / 256, 256>>>((const float4*)key);
    wsplit_kernel<<<gw, dim3(32, 8)>>>(Wk);
    hgemm_kernel<1,1><<<gg, 256>>>(bk, nullptr);

    asplit_kernel<0><<<n4 / 256, 256>>>((const float4*)value);
    wsplit_kernel<<<gw, dim3(32, 8)>>>(Wv);
    hgemm_kernel<0,2><<<gg, 256>>>(bv, nullptr);

    attn_kernel<<<dim3(SEQ / 64, BATCH * NH), 256>>>();

    asplit_kernel<1><<<n4 / 256, 256>>>(nullptr);   // src = g_att (device-side)
    wsplit_kernel<<<gw, dim3(32, 8)>>>(Wo);
    hgemm_kernel<0,3><<<gg, 256>>>(bo, out);
}

// round 6
// speedup vs baseline: 2.6042x; 1.5948x over previous
#include <cuda_runtime.h>
#include <cuda_bf16.h>
#include <math.h>
#include <stdint.h>

#define DIMC 1024
#define NH 16
#define HD 64
#define BATCH 4
#define SEQ 2048
#define BT (BATCH*SEQ)

// ---------------- scratch (allocation-free) ----------------
__device__ float g_q[(size_t)BATCH*NH*SEQ*HD];
__device__ float g_k[(size_t)BATCH*NH*SEQ*HD];
__device__ float g_v[(size_t)BATCH*NH*SEQ*HD];
__device__ float g_att[(size_t)BT*DIMC];
__device__ __nv_bfloat16 g_ahi[(size_t)BT*DIMC];
__device__ __nv_bfloat16 g_alo[(size_t)BT*DIMC];
__device__ __nv_bfloat16 g_whi[(size_t)DIMC*DIMC];   // [N,K]
__device__ __nv_bfloat16 g_wlo[(size_t)DIMC*DIMC];   // [N,K]
__device__ float2 g_rope[SEQ*32];                    // (cos,sin) per (t, d/2)

// ---------------- mma.sync helper (sm_80+ PTX, compute_103-safe) ----------------
__device__ __forceinline__ void mma16816(float* d, const uint32_t* a, uint32_t b0, uint32_t b1) {
    asm volatile("mma.sync.aligned.m16n8k16.row.col.f32.bf16.bf16.f32 "
                 "{%0,%1,%2,%3}, {%4,%5,%6,%7}, {%8,%9}, {%0,%1,%2,%3};"
                 : "+f"(d[0]), "+f"(d[1]), "+f"(d[2]), "+f"(d[3])
                 : "r"(a[0]), "r"(a[1]), "r"(a[2]), "r"(a[3]), "r"(b0), "r"(b1));
}

__device__ __forceinline__ uint32_t packbf(float a, float b) {
    __nv_bfloat162 t = __floats2bfloat162_rn(a, b);   // x=a (low), y=b (high)
    return *(uint32_t*)&t;
}
__device__ __forceinline__ float flo(float x) {
    return x - __bfloat162float(__float2bfloat16(x));
}
// exp2 on the FMA/ALU pipes only (no MUFU). t expected <= ~0; clamped at -30.
__device__ __forceinline__ float fexp2(float t) {
    t = fmaxf(t, -30.0f);
    float r = t + 12582912.0f;                        // round-to-nearest-int trick
    int n = __float_as_int(r) - 0x4B400000;
    float f = t - (r - 12582912.0f);                  // frac in [-0.5, 0.5]
    float p = 1.3333558146e-3f;
    p = fmaf(p, f, 9.6181291077e-3f);
    p = fmaf(p, f, 5.5504108664e-2f);
    p = fmaf(p, f, 2.4022650696e-1f);
    p = fmaf(p, f, 6.9314718056e-1f);
    p = fmaf(p, f, 1.0f);
    return __int_as_float(__float_as_int(p) + (n << 23));
}

// ---------------- helper kernels ----------------
__global__ __launch_bounds__(256) void rope_table_kernel() {
    int idx = blockIdx.x * 256 + threadIdx.x;        // 65536 = 2048*32
    int t = idx >> 5, f = idx & 31;
    double invf = 1.0 / pow(10000.0, (double)(2 * f) / 64.0);
    float ang = (float)t * (float)invf;
    g_rope[idx] = make_float2((float)cos((double)ang), (float)sin((double)ang));
}

template<int FROMATT>
__global__ __launch_bounds__(256) void asplit_kernel(const float4* __restrict__ in) {
    const float4* src = FROMATT ? (const float4*)g_att : in;
    int i = blockIdx.x * 256 + threadIdx.x;           // n4 = BT*DIMC/4
    float4 v = src[i];
    float vv[4] = {v.x, v.y, v.z, v.w};
    __nv_bfloat16 h[4], l[4];
    #pragma unroll
    for (int j = 0; j < 4; j++) {
        h[j] = __float2bfloat16(vv[j]);
        l[j] = __float2bfloat16(vv[j] - __bfloat162float(h[j]));
    }
    *(uint2*)(g_ahi + 4 * (size_t)i) = *(uint2*)h;
    *(uint2*)(g_alo + 4 * (size_t)i) = *(uint2*)l;
}

__global__ __launch_bounds__(256) void wsplit_kernel(const float* __restrict__ W) {
    __shared__ float tile[32][33];
    int n0 = blockIdx.x * 32, k0 = blockIdx.y * 32;
    int x = threadIdx.x, y0 = threadIdx.y;            // block (32,8)
    for (int j = y0; j < 32; j += 8)
        tile[j][x] = W[(size_t)(k0 + j) * DIMC + n0 + x];
    __syncthreads();
    for (int j = y0; j < 32; j += 8) {
        float v = tile[x][j];
        __nv_bfloat16 h = __float2bfloat16(v);
        size_t o = (size_t)(n0 + j) * DIMC + k0 + x;
        g_whi[o] = h;
        g_wlo[o] = __float2bfloat16(v - __bfloat162float(h));
    }
}

// ---------------- HMMA GEMM (unchanged from passing R5) ----------------
#define S32 20   // uint32 stride per row

template<int DOROPE, int DEST>
__global__ __launch_bounds__(256) void hgemm_kernel(const float* __restrict__ bias,
                                                    float* __restrict__ outp)
{
    __shared__ __align__(16) uint32_t sAh[128 * S32];
    __shared__ __align__(16) uint32_t sAl[128 * S32];
    __shared__ __align__(16) uint32_t sBh[128 * S32];
    __shared__ __align__(16) uint32_t sBl[128 * S32];

    const int tid  = threadIdx.x;
    const int lane = tid & 31;
    const int wid  = tid >> 5;
    const int wm = wid & 1;
    const int wn = wid >> 1;
    const int m0 = blockIdx.y << 7, n0 = blockIdx.x << 7;

    float acc[4][4][4];
    #pragma unroll
    for (int i = 0; i < 4; i++)
        #pragma unroll
        for (int j = 0; j < 4; j++)
            #pragma unroll
            for (int r = 0; r < 4; r++) acc[i][j][r] = 0.f;

    const int qrow = lane >> 2;
    const int qk   = lane & 3;

    for (int k0 = 0; k0 < DIMC; k0 += 32) {
        #pragma unroll
        for (int it = 0; it < 2; it++) {
            int i = tid + it * 256;
            int row = i >> 2, seg = i & 3;
            size_t ga = (size_t)(m0 + row) * DIMC + k0 + seg * 8;
            size_t gb = (size_t)(n0 + row) * DIMC + k0 + seg * 8;
            int so = row * S32 + seg * 4;
            *(uint4*)(sAh + so) = *(const uint4*)(g_ahi + ga);
            *(uint4*)(sAl + so) = *(const uint4*)(g_alo + ga);
            *(uint4*)(sBh + so) = *(const uint4*)(g_whi + gb);
            *(uint4*)(sBl + so) = *(const uint4*)(g_wlo + gb);
        }
        __syncthreads();

        #pragma unroll
        for (int ks2 = 0; ks2 < 16; ks2 += 8) {
            uint32_t ah[4][4], al[4][4], bh[4][2], bl[4][2];
            #pragma unroll
            for (int mt = 0; mt < 4; mt++) {
                int r0 = (wm * 64 + mt * 16 + qrow) * S32 + ks2 + qk;
                int r8 = r0 + 8 * S32;
                ah[mt][0] = sAh[r0];     ah[mt][1] = sAh[r8];
                ah[mt][2] = sAh[r0 + 4]; ah[mt][3] = sAh[r8 + 4];
                al[mt][0] = sAl[r0];     al[mt][1] = sAl[r8];
                al[mt][2] = sAl[r0 + 4]; al[mt][3] = sAl[r8 + 4];
            }
            #pragma unroll
            for (int nt = 0; nt < 4; nt++) {
                int nr = (wn * 32 + nt * 8 + qrow) * S32 + ks2 + qk;
                bh[nt][0] = sBh[nr]; bh[nt][1] = sBh[nr + 4];
                bl[nt][0] = sBl[nr]; bl[nt][1] = sBl[nr + 4];
            }
            #pragma unroll
            for (int mt = 0; mt < 4; mt++)
                #pragma unroll
                for (int nt = 0; nt < 4; nt++) {
                    mma16816(acc[mt][nt], ah[mt], bh[nt][0], bh[nt][1]);
                    mma16816(acc[mt][nt], ah[mt], bl[nt][0], bl[nt][1]);
                    mma16816(acc[mt][nt], al[mt], bh[nt][0], bh[nt][1]);
                }
        }
        __syncthreads();
    }

    const int quad = lane >> 2, tc = lane & 3;
    #pragma unroll
    for (int mt = 0; mt < 4; mt++) {
        #pragma unroll
        for (int nt = 0; nt < 4; nt++) {
            #pragma unroll
            for (int half = 0; half < 2; half++) {
                int m = m0 + wm * 64 + mt * 16 + quad + half * 8;
                int n = n0 + wn * 32 + nt * 8 + tc * 2;
                float v0 = acc[mt][nt][half * 2]     + bias[n];
                float v1 = acc[mt][nt][half * 2 + 1] + bias[n + 1];
                if (DEST <= 2) {
                    float* out = (DEST == 0) ? g_q : (DEST == 1) ? g_k : g_v;
                    int b = m >> 11, t = m & (SEQ - 1);
                    int h = n >> 6, d = n & 63;
                    float oe, oo;
                    if (DOROPE) {
                        float2 cs = g_rope[t * 32 + (d >> 1)];
                        oe = v0 * cs.x - v1 * cs.y;
                        oo = v0 * cs.y + v1 * cs.x;
                    } else { oe = v0; oo = v1; }
                    size_t base = ((size_t)(b * NH + h) * SEQ + t) * HD + d;
                    out[base]     = oe;
                    out[base + 1] = oo;
                } else {
                    size_t base = (size_t)m * DIMC + n;
                    outp[base]     = v0;
                    outp[base + 1] = v1;
                }
            }
        }
    }
}

// ---------------- tensorized causal flash attention ----------------
// Br=128 (8 warps x 16 rows), Bc=64, D=64. 3-term bf16-split mma for QK^T and PV.
// P pipeline stays in registers. exp2 via FFMA-pipe polynomial (no MUFU).
// Padded smem stride 36 u32 (72 halves) -> conflict-free quad-pattern LDS.
#define SV 36
#define QHOF 0
#define QLOF 4608
#define KHOF 9216
#define KLOF 11520
#define VHOF 13824
#define VLOF 16128
#define ATT_SMEM_BYTES (18432*4)

__global__ __launch_bounds__(256) void attn_kernel()
{
    extern __shared__ uint32_t smu[];

    const int tid  = threadIdx.x;
    const int lane = tid & 31;
    const int wid  = tid >> 5;
    const int bh   = blockIdx.y;
    const int m0   = ((int)gridDim.x - 1 - (int)blockIdx.x) * 128;  // big blocks first

    const float* Qb = g_q + (size_t)bh * SEQ * HD;
    const float* Kb = g_k + (size_t)bh * SEQ * HD;
    const float* Vb = g_v + (size_t)bh * SEQ * HD;

    // ---- load Q tile (128x64) as hi/lo bf16, padded ----
    #pragma unroll
    for (int j = 0; j < 8; j++) {
        int idx = tid + j * 256;                 // 2048 float4
        int r = idx >> 4, fg = idx & 15;
        float4 q = *(const float4*)(Qb + (size_t)(m0 + r) * HD + fg * 4);
        int o = r * SV + fg * 2;
        smu[QHOF + o]     = packbf(q.x, q.y);
        smu[QHOF + o + 1] = packbf(q.z, q.w);
        smu[QLOF + o]     = packbf(flo(q.x), flo(q.y));
        smu[QLOF + o + 1] = packbf(flo(q.z), flo(q.w));
    }

    float oacc[8][4];
    #pragma unroll
    for (int nt = 0; nt < 8; nt++)
        #pragma unroll
        for (int e = 0; e < 4; e++) oacc[nt][e] = 0.f;
    float mr[2] = {-1e30f, -1e30f};
    float lr[2] = {0.f, 0.f};

    const int qr = lane >> 2, qc = lane & 3;
    const int rowbase = m0 + wid * 16;
    const int ntiles = m0 / 64 + 2;

    for (int tix = 0; tix < ntiles; tix++) {
        int s0 = tix * 64;
        __syncthreads();   // previous tile's LDS reads done before overwrite

        // ---- K tile (64x64) ----
        #pragma unroll
        for (int j = 0; j < 4; j++) {
            int idx = tid + j * 256;             // 1024 float4
            int r = idx >> 4, fg = idx & 15;
            float4 k = *(const float4*)(Kb + (size_t)(s0 + r) * HD + fg * 4);
            int o = r * SV + fg * 2;
            smu[KHOF + o]     = packbf(k.x, k.y);
            smu[KHOF + o + 1] = packbf(k.z, k.w);
            smu[KLOF + o]     = packbf(flo(k.x), flo(k.y));
            smu[KLOF + o + 1] = packbf(flo(k.z), flo(k.w));
        }
        // ---- V tile transposed: Vt[dim][keypair] via shfl pair-exchange ----
        #pragma unroll
        for (int j = 0; j < 4; j++) {
            int key = j * 16 + 2 * wid + (lane >> 4);
            int kp  = j * 8 + wid;
            #pragma unroll
            for (int s = 0; s < 4; s++) {
                int d = (lane & 15) + s * 16;
                float v  = Vb[(size_t)(s0 + key) * HD + d];
                float pv = __shfl_xor_sync(0xffffffffu, v, 16);
                float ev = (lane < 16) ? v : pv;    // even key
                float ov = (lane < 16) ? pv : v;    // odd key
                if (lane < 16)
                    smu[VHOF + d * SV + kp] = packbf(ev, ov);
                else
                    smu[VLOF + d * SV + kp] = packbf(flo(ev), flo(ov));
            }
        }
        __syncthreads();

        if (s0 <= rowbase + 15) {   // warp has unmasked work in this tile
            // ---- S = Q K^T ----
            float sacc[8][4];
            #pragma unroll
            for (int nt = 0; nt < 8; nt++)
                #pragma unroll
                for (int e = 0; e < 4; e++) sacc[nt][e] = 0.f;

            #pragma unroll
            for (int ks = 0; ks < 4; ks++) {
                int ab = (wid * 16 + qr) * SV + ks * 8 + qc;
                uint32_t ah[4], al[4];
                ah[0] = smu[QHOF + ab];           ah[1] = smu[QHOF + ab + 8 * SV];
                ah[2] = smu[QHOF + ab + 4];       ah[3] = smu[QHOF + ab + 8 * SV + 4];
                al[0] = smu[QLOF + ab];           al[1] = smu[QLOF + ab + 8 * SV];
                al[2] = smu[QLOF + ab + 4];       al[3] = smu[QLOF + ab + 8 * SV + 4];
                #pragma unroll
                for (int nt = 0; nt < 8; nt++) {
                    int bb = (nt * 8 + qr) * SV + ks * 8 + qc;
                    uint32_t kh0 = smu[KHOF + bb], kh1 = smu[KHOF + bb + 4];
                    uint32_t kl0 = smu[KLOF + bb], kl1 = smu[KLOF + bb + 4];
                    mma16816(sacc[nt], ah, kh0, kh1);
                    mma16816(sacc[nt], ah, kl0, kl1);
                    mma16816(sacc[nt], al, kh0, kh1);
                }
            }

            // ---- causal mask (raw-score units) ----
            if (s0 + 63 > rowbase) {
                int rA = rowbase + qr, rB = rA + 8;
                #pragma unroll
                for (int nt = 0; nt < 8; nt++) {
                    int c0 = s0 + nt * 8 + qc * 2;
                    if (c0 > rA)     sacc[nt][0] = -1e30f;
                    if (c0 + 1 > rA) sacc[nt][1] = -1e30f;
                    if (c0 > rB)     sacc[nt][2] = -1e30f;
                    if (c0 + 1 > rB) sacc[nt][3] = -1e30f;
                }
            }

            // ---- online softmax (FFMA-pipe exp2) ----
            float mxA = -1e30f, mxB = -1e30f;
            #pragma unroll
            for (int nt = 0; nt < 8; nt++) {
                mxA = fmaxf(mxA, fmaxf(sacc[nt][0], sacc[nt][1]));
                mxB = fmaxf(mxB, fmaxf(sacc[nt][2], sacc[nt][3]));
            }
            mxA = fmaxf(mxA, __shfl_xor_sync(0xffffffffu, mxA, 1));
            mxA = fmaxf(mxA, __shfl_xor_sync(0xffffffffu, mxA, 2));
            mxB = fmaxf(mxB, __shfl_xor_sync(0xffffffffu, mxB, 1));
            mxB = fmaxf(mxB, __shfl_xor_sync(0xffffffffu, mxB, 2));
            mxA *= 0.125f; mxB *= 0.125f;

            float mnA = fmaxf(mr[0], mxA), mnB = fmaxf(mr[1], mxB);
            float corrA = fexp2((mr[0] - mnA) * 1.44269504f);
            float corrB = fexp2((mr[1] - mnB) * 1.44269504f);
            mr[0] = mnA; mr[1] = mnB;
            float nbA = mnA * 1.44269504f, nbB = mnB * 1.44269504f;

            const float C1 = 0.125f * 1.44269504f;   // score scale * log2e
            float suA = 0.f, suB = 0.f;
            #pragma unroll
            for (int nt = 0; nt < 8; nt++) {
                float p0 = fexp2(fmaf(sacc[nt][0], C1, -nbA));
                float p1 = fexp2(fmaf(sacc[nt][1], C1, -nbA));
                float p2 = fexp2(fmaf(sacc[nt][2], C1, -nbB));
                float p3 = fexp2(fmaf(sacc[nt][3], C1, -nbB));
                sacc[nt][0] = p0; sacc[nt][1] = p1;
                sacc[nt][2] = p2; sacc[nt][3] = p3;
                suA += p0 + p1; suB += p2 + p3;
            }
            suA += __shfl_xor_sync(0xffffffffu, suA, 1);
            suA += __shfl_xor_sync(0xffffffffu, suA, 2);
            suB += __shfl_xor_sync(0xffffffffu, suB, 1);
            suB += __shfl_xor_sync(0xffffffffu, suB, 2);
            lr[0] = lr[0] * corrA + suA;
            lr[1] = lr[1] * corrB + suB;
            #pragma unroll
            for (int nt = 0; nt < 8; nt++) {
                oacc[nt][0] *= corrA; oacc[nt][1] *= corrA;
                oacc[nt][2] *= corrB; oacc[nt][3] *= corrB;
            }

            // ---- P -> bf16 hi/lo A-fragments (register-only) ----
            uint32_t ph[4][4], pl[4][4];
            #pragma unroll
            for (int kk = 0; kk < 4; kk++) {
                float a0 = sacc[2*kk][0],   a1 = sacc[2*kk][1];
                float a2 = sacc[2*kk][2],   a3 = sacc[2*kk][3];
                float b0 = sacc[2*kk+1][0], b1 = sacc[2*kk+1][1];
                float b2 = sacc[2*kk+1][2], b3 = sacc[2*kk+1][3];
                ph[kk][0] = packbf(a0, a1); ph[kk][1] = packbf(a2, a3);
                ph[kk][2] = packbf(b0, b1); ph[kk][3] = packbf(b2, b3);
                pl[kk][0] = packbf(flo(a0), flo(a1)); pl[kk][1] = packbf(flo(a2), flo(a3));
                pl[kk][2] = packbf(flo(b0), flo(b1)); pl[kk][3] = packbf(flo(b2), flo(b3));
            }

            // ---- O += P V ----
            #pragma unroll
            for (int nt = 0; nt < 8; nt++) {
                #pragma unroll
                for (int kk = 0; kk < 4; kk++) {
                    int vb = (nt * 8 + qr) * SV + kk * 8 + qc;
                    uint32_t vh0 = smu[VHOF + vb], vh1 = smu[VHOF + vb + 4];
                    uint32_t vl0 = smu[VLOF + vb], vl1 = smu[VLOF + vb + 4];
                    mma16816(oacc[nt], ph[kk], vh0, vh1);
                    mma16816(oacc[nt], ph[kk], vl0, vl1);
                    mma16816(oacc[nt], pl[kk], vh0, vh1);
                }
            }
        }
    }

    // ---- epilogue: O/l -> g_att [b, t, h*64+d] ----
    float ivA = 1.0f / lr[0], ivB = 1.0f / lr[1];
    int b = bh >> 4, h = bh & 15;
    int rA = rowbase + qr, rB = rA + 8;
    #pragma unroll
    for (int nt = 0; nt < 8; nt++) {
        int d = nt * 8 + qc * 2;
        *(float2*)&g_att[((size_t)(b * SEQ + rA)) * DIMC + h * HD + d] =
            make_float2(oacc[nt][0] * ivA, oacc[nt][1] * ivA);
        *(float2*)&g_att[((size_t)(b * SEQ + rB)) * DIMC + h * HD + d] =
            make_float2(oacc[nt][2] * ivB, oacc[nt][3] * ivB);
    }
}

// ---------------- launch ----------------
extern "C" void kernel_launch(void* const* d_in, const int* in_sizes, int n_in,
                              void* d_out, int out_size)
{
    const float* query = (const float*)d_in[0];
    const float* key   = (const float*)d_in[1];
    const float* value = (const float*)d_in[2];
    const float* Wq = (const float*)d_in[3];
    const float* bq = (const float*)d_in[4];
    const float* Wk = (const float*)d_in[5];
    const float* bk = (const float*)d_in[6];
    const float* Wv = (const float*)d_in[7];
    const float* bv = (const float*)d_in[8];
    const float* Wo = (const float*)d_in[9];
    const float* bo = (const float*)d_in[10];
    float* out = (float*)d_out;

    cudaFuncSetAttribute(attn_kernel, cudaFuncAttributeMaxDynamicSharedMemorySize,
                         ATT_SMEM_BYTES);

    dim3 gg(DIMC / 128, BT / 128);   // (8, 64)
    dim3 gw(DIMC / 32, DIMC / 32);   // (32, 32)
    int n4 = BT * DIMC / 4;

    rope_table_kernel<<<SEQ * 32 / 256, 256>>>();

    asplit_kernel<0><<<n4 / 256, 256>>>((const float4*)query);
    wsplit_kernel<<<gw, dim3(32, 8)>>>(Wq);
    hgemm_kernel<1,0><<<gg, 256>>>(bq, nullptr);

    asplit_kernel<0><<<n4 / 256, 256>>>((const float4*)key);
    wsplit_kernel<<<gw, dim3(32, 8)>>>(Wk);
    hgemm_kernel<1,1><<<gg, 256>>>(bk, nullptr);

    asplit_kernel<0><<<n4 / 256, 256>>>((const float4*)value);
    wsplit_kernel<<<gw, dim3(32, 8)>>>(Wv);
    hgemm_kernel<0,2><<<gg, 256>>>(bv, nullptr);

    attn_kernel<<<dim3(SEQ / 128, BATCH * NH), 256, ATT_SMEM_BYTES>>>();

    asplit_kernel<1><<<n4 / 256, 256>>>(nullptr);   // src = g_att (device-side)
    wsplit_kernel<<<gw, dim3(32, 8)>>>(Wo);
    hgemm_kernel<0,3><<<gg, 256>>>(bo, out);
}

// round 7
// speedup vs baseline: 2.9219x; 1.1220x over previous
#include <cuda_runtime.h>
#include <cuda_bf16.h>
#include <math.h>
#include <stdint.h>

#define DIMC 1024
#define NH 16
#define HD 64
#define BATCH 4
#define SEQ 2048
#define BT (BATCH*SEQ)
#define MK ((size_t)BT*DIMC)     // 8M elements

// ---------------- scratch (allocation-free) ----------------
__device__ float g_q[(size_t)BATCH*NH*SEQ*HD];
__device__ float g_k[(size_t)BATCH*NH*SEQ*HD];
__device__ float g_v[(size_t)BATCH*NH*SEQ*HD];
__device__ float g_att[(size_t)BT*DIMC];
__device__ __nv_bfloat16 g_ahi[3*MK];                  // slots: 0=q/att, 1=k, 2=v
__device__ __nv_bfloat16 g_alo[3*MK];
__device__ __nv_bfloat16 g_whi[4*(size_t)DIMC*DIMC];   // slots: q,k,v,o  [N,K]
__device__ __nv_bfloat16 g_wlo[4*(size_t)DIMC*DIMC];
__device__ float2 g_rope[SEQ*32];                      // (cos,sin) per (t, d/2)

// ---------------- PTX helpers (sm_80+ features only; compute_103-safe) ----------------
__device__ __forceinline__ uint32_t smem_u32(const void* p) {
    uint32_t a;
    asm("{ .reg .u64 t; cvta.to.shared.u64 t, %1; cvt.u32.u64 %0, t; }" : "=r"(a) : "l"(p));
    return a;
}
__device__ __forceinline__ void cpasync16(uint32_t saddr, const void* g) {
    asm volatile("cp.async.cg.shared.global [%0], [%1], 16;" :: "r"(saddr), "l"(g));
}
__device__ __forceinline__ void mma16816(float* d, const uint32_t* a, uint32_t b0, uint32_t b1) {
    asm volatile("mma.sync.aligned.m16n8k16.row.col.f32.bf16.bf16.f32 "
                 "{%0,%1,%2,%3}, {%4,%5,%6,%7}, {%8,%9}, {%0,%1,%2,%3};"
                 : "+f"(d[0]), "+f"(d[1]), "+f"(d[2]), "+f"(d[3])
                 : "r"(a[0]), "r"(a[1]), "r"(a[2]), "r"(a[3]), "r"(b0), "r"(b1));
}
__device__ __forceinline__ uint32_t packbf(float a, float b) {
    __nv_bfloat162 t = __floats2bfloat162_rn(a, b);
    return *(uint32_t*)&t;
}
__device__ __forceinline__ float flo(float x) {
    return x - __bfloat162float(__float2bfloat16(x));
}
// exp2 on the FMA/ALU pipes only (no MUFU); input <= ~0, clamped at -30.
__device__ __forceinline__ float fexp2(float t) {
    t = fmaxf(t, -30.0f);
    float r = t + 12582912.0f;
    int n = __float_as_int(r) - 0x4B400000;
    float f = t - (r - 12582912.0f);
    float p = 1.3333558146e-3f;
    p = fmaf(p, f, 9.6181291077e-3f);
    p = fmaf(p, f, 5.5504108664e-2f);
    p = fmaf(p, f, 2.4022650696e-1f);
    p = fmaf(p, f, 6.9314718056e-1f);
    p = fmaf(p, f, 1.0f);
    return __int_as_float(__float_as_int(p) + (n << 23));
}

// ---------------- helper kernels ----------------
__global__ __launch_bounds__(256) void rope_table_kernel() {
    int idx = blockIdx.x * 256 + threadIdx.x;
    int t = idx >> 5, f = idx & 31;
    double invf = 1.0 / pow(10000.0, (double)(2 * f) / 64.0);
    float ang = (float)t * (float)invf;
    g_rope[idx] = make_float2((float)cos((double)ang), (float)sin((double)ang));
}

// split q/k/v inputs into bf16 hi/lo, slots 0/1/2 (z = blockIdx.y)
__global__ __launch_bounds__(256) void asplit3_kernel(const float4* __restrict__ q,
                                                      const float4* __restrict__ k,
                                                      const float4* __restrict__ v) {
    int z = blockIdx.y;
    const float4* src = (z == 0) ? q : (z == 1) ? k : v;
    size_t i = blockIdx.x * 256 + threadIdx.x;
    float4 val = src[i];
    float vv[4] = {val.x, val.y, val.z, val.w};
    __nv_bfloat16 h[4], l[4];
    #pragma unroll
    for (int j = 0; j < 4; j++) {
        h[j] = __float2bfloat16(vv[j]);
        l[j] = __float2bfloat16(vv[j] - __bfloat162float(h[j]));
    }
    size_t o = z * MK + 4 * i;
    *(uint2*)(g_ahi + o) = *(uint2*)h;
    *(uint2*)(g_alo + o) = *(uint2*)l;
}

// split g_att (device symbol) into slot 0
__global__ __launch_bounds__(256) void asplit_att_kernel() {
    size_t i = blockIdx.x * 256 + threadIdx.x;
    float4 val = ((const float4*)g_att)[i];
    float vv[4] = {val.x, val.y, val.z, val.w};
    __nv_bfloat16 h[4], l[4];
    #pragma unroll
    for (int j = 0; j < 4; j++) {
        h[j] = __float2bfloat16(vv[j]);
        l[j] = __float2bfloat16(vv[j] - __bfloat162float(h[j]));
    }
    *(uint2*)(g_ahi + 4 * i) = *(uint2*)h;
    *(uint2*)(g_alo + 4 * i) = *(uint2*)l;
}

// W [K,N] fp32 -> transposed (hi,lo) bf16 [N,K], slot z
__global__ __launch_bounds__(256) void wsplit4_kernel(const float* __restrict__ Wq,
                                                      const float* __restrict__ Wk,
                                                      const float* __restrict__ Wv,
                                                      const float* __restrict__ Wo) {
    __shared__ float tile[32][33];
    int z = blockIdx.z;
    const float* W = (z == 0) ? Wq : (z == 1) ? Wk : (z == 2) ? Wv : Wo;
    size_t wof = (size_t)z * DIMC * DIMC;
    int n0 = blockIdx.x * 32, k0 = blockIdx.y * 32;
    int x = threadIdx.x, y0 = threadIdx.y;
    for (int j = y0; j < 32; j += 8)
        tile[j][x] = W[(size_t)(k0 + j) * DIMC + n0 + x];
    __syncthreads();
    for (int j = y0; j < 32; j += 8) {
        float v = tile[x][j];
        __nv_bfloat16 h = __float2bfloat16(v);
        size_t o = wof + (size_t)(n0 + j) * DIMC + k0 + x;
        g_whi[o] = h;
        g_wlo[o] = __float2bfloat16(v - __bfloat162float(h));
    }
}

// ---------------- cp.async double-buffered HMMA GEMM ----------------
// C[8192,1024] = A W + b, 3-term bf16 split. CTA 128x128, BK=32, 8 warps.
// MODE 0: fused QKV (blockIdx.z = 0/1/2 -> src slot, W slot, dest, RoPE)
// MODE 1: final projection (A slot 0 from g_att, W slot 3, writes outp)
#define S32 20                       // u32 stride per smem row
#define ARR_B (128*S32*4)            // bytes per array (10240)
#define STAGE_B (4*ARR_B)            // bytes per stage (40960)
#define GSMEM_BYTES (2*STAGE_B)      // 81920

template<int MODE>
__global__ __launch_bounds__(256, 2) void pgemm_kernel(const float* __restrict__ b0p,
                                                       const float* __restrict__ b1p,
                                                       const float* __restrict__ b2p,
                                                       float* __restrict__ outp)
{
    extern __shared__ uint32_t smu[];
    const uint32_t su = smem_u32(smu);

    const int tid  = threadIdx.x;
    const int lane = tid & 31;
    const int wid  = tid >> 5;
    const int wm = wid & 1;
    const int wn = wid >> 1;
    const int m0 = blockIdx.y << 7, n0 = blockIdx.x << 7;
    const int z = (MODE == 0) ? blockIdx.z : 3;

    const __nv_bfloat16* ahi = g_ahi + ((MODE == 0) ? (size_t)z * MK : 0) + (size_t)m0 * DIMC;
    const __nv_bfloat16* alo = g_alo + ((MODE == 0) ? (size_t)z * MK : 0) + (size_t)m0 * DIMC;
    const __nv_bfloat16* whi = g_whi + (size_t)z * DIMC * DIMC + (size_t)n0 * DIMC;
    const __nv_bfloat16* wlo = g_wlo + (size_t)z * DIMC * DIMC + (size_t)n0 * DIMC;
    const float* bias = (MODE == 1) ? b0p : (z == 0) ? b0p : (z == 1) ? b1p : b2p;

    // per-thread load geometry (2 uint4 per array per stage)
    const int l_row0 = tid >> 2, l_seg = tid & 3;
    const int l_row1 = l_row0 + 64;

    float acc[4][4][4];
    #pragma unroll
    for (int i = 0; i < 4; i++)
        #pragma unroll
        for (int j = 0; j < 4; j++)
            #pragma unroll
            for (int r = 0; r < 4; r++) acc[i][j][r] = 0.f;

    const int qrow = lane >> 2;
    const int qk   = lane & 3;

    // ---- pipelined loads ----
    auto issue = [&](int c, int buf) {
        int k0 = c << 5;
        uint32_t base = su + buf * STAGE_B;
        #pragma unroll
        for (int rr = 0; rr < 2; rr++) {
            int row = rr ? l_row1 : l_row0;
            size_t g = (size_t)row * DIMC + k0 + l_seg * 8;
            uint32_t so = (uint32_t)(row * S32 + l_seg * 4) * 4;
            cpasync16(base + 0 * ARR_B + so, ahi + g);
            cpasync16(base + 1 * ARR_B + so, alo + g);
            cpasync16(base + 2 * ARR_B + so, whi + g);
            cpasync16(base + 3 * ARR_B + so, wlo + g);
        }
        asm volatile("cp.async.commit_group;");
    };

    issue(0, 0);
    for (int c = 0; c < 32; c++) {
        int buf = c & 1;
        if (c < 31) {
            issue(c + 1, buf ^ 1);
            asm volatile("cp.async.wait_group 1;");
        } else {
            asm volatile("cp.async.wait_group 0;");
        }
        __syncthreads();

        const uint32_t* sAh = smu + buf * (STAGE_B/4);
        const uint32_t* sAl = sAh + (ARR_B/4);
        const uint32_t* sBh = sAl + (ARR_B/4);
        const uint32_t* sBl = sBh + (ARR_B/4);

        #pragma unroll
        for (int ks2 = 0; ks2 < 16; ks2 += 8) {
            uint32_t ah[4][4], al[4][4], bh[4][2], bl[4][2];
            #pragma unroll
            for (int mt = 0; mt < 4; mt++) {
                int r0 = (wm * 64 + mt * 16 + qrow) * S32 + ks2 + qk;
                int r8 = r0 + 8 * S32;
                ah[mt][0] = sAh[r0];     ah[mt][1] = sAh[r8];
                ah[mt][2] = sAh[r0 + 4]; ah[mt][3] = sAh[r8 + 4];
                al[mt][0] = sAl[r0];     al[mt][1] = sAl[r8];
                al[mt][2] = sAl[r0 + 4]; al[mt][3] = sAl[r8 + 4];
            }
            #pragma unroll
            for (int nt = 0; nt < 4; nt++) {
                int nr = (wn * 32 + nt * 8 + qrow) * S32 + ks2 + qk;
                bh[nt][0] = sBh[nr]; bh[nt][1] = sBh[nr + 4];
                bl[nt][0] = sBl[nr]; bl[nt][1] = sBl[nr + 4];
            }
            #pragma unroll
            for (int mt = 0; mt < 4; mt++)
                #pragma unroll
                for (int nt = 0; nt < 4; nt++) {
                    mma16816(acc[mt][nt], ah[mt], bh[nt][0], bh[nt][1]);
                    mma16816(acc[mt][nt], ah[mt], bl[nt][0], bl[nt][1]);
                    mma16816(acc[mt][nt], al[mt], bh[nt][0], bh[nt][1]);
                }
        }
        __syncthreads();
    }

    const int quad = lane >> 2, tc = lane & 3;
    #pragma unroll
    for (int mt = 0; mt < 4; mt++) {
        #pragma unroll
        for (int nt = 0; nt < 4; nt++) {
            #pragma unroll
            for (int half = 0; half < 2; half++) {
                int m = m0 + wm * 64 + mt * 16 + quad + half * 8;
                int n = n0 + wn * 32 + nt * 8 + tc * 2;
                float v0 = acc[mt][nt][half * 2]     + bias[n];
                float v1 = acc[mt][nt][half * 2 + 1] + bias[n + 1];
                if (MODE == 0) {
                    float* out = (z == 0) ? g_q : (z == 1) ? g_k : g_v;
                    int b = m >> 11, t = m & (SEQ - 1);
                    int h = n >> 6, d = n & 63;
                    float oe, oo;
                    if (z < 2) {
                        float2 cs = g_rope[t * 32 + (d >> 1)];
                        oe = v0 * cs.x - v1 * cs.y;
                        oo = v0 * cs.y + v1 * cs.x;
                    } else { oe = v0; oo = v1; }
                    size_t base = ((size_t)(b * NH + h) * SEQ + t) * HD + d;
                    out[base]     = oe;
                    out[base + 1] = oo;
                } else {
                    size_t base = (size_t)m * DIMC + n;
                    outp[base]     = v0;
                    outp[base + 1] = v1;
                }
            }
        }
    }
}

// ---------------- tensorized causal flash attention (unchanged, proven R6) ----------------
#define SV 36
#define QHOF 0
#define QLOF 4608
#define KHOF 9216
#define KLOF 11520
#define VHOF 13824
#define VLOF 16128
#define ATT_SMEM_BYTES (18432*4)

__global__ __launch_bounds__(256) void attn_kernel()
{
    extern __shared__ uint32_t smu[];

    const int tid  = threadIdx.x;
    const int lane = tid & 31;
    const int wid  = tid >> 5;
    const int bh   = blockIdx.y;
    const int m0   = ((int)gridDim.x - 1 - (int)blockIdx.x) * 128;

    const float* Qb = g_q + (size_t)bh * SEQ * HD;
    const float* Kb = g_k + (size_t)bh * SEQ * HD;
    const float* Vb = g_v + (size_t)bh * SEQ * HD;

    #pragma unroll
    for (int j = 0; j < 8; j++) {
        int idx = tid + j * 256;
        int r = idx >> 4, fg = idx & 15;
        float4 q = *(const float4*)(Qb + (size_t)(m0 + r) * HD + fg * 4);
        int o = r * SV + fg * 2;
        smu[QHOF + o]     = packbf(q.x, q.y);
        smu[QHOF + o + 1] = packbf(q.z, q.w);
        smu[QLOF + o]     = packbf(flo(q.x), flo(q.y));
        smu[QLOF + o + 1] = packbf(flo(q.z), flo(q.w));
    }

    float oacc[8][4];
    #pragma unroll
    for (int nt = 0; nt < 8; nt++)
        #pragma unroll
        for (int e = 0; e < 4; e++) oacc[nt][e] = 0.f;
    float mr[2] = {-1e30f, -1e30f};
    float lr[2] = {0.f, 0.f};

    const int qr = lane >> 2, qc = lane & 3;
    const int rowbase = m0 + wid * 16;
    const int ntiles = m0 / 64 + 2;

    for (int tix = 0; tix < ntiles; tix++) {
        int s0 = tix * 64;
        __syncthreads();

        #pragma unroll
        for (int j = 0; j < 4; j++) {
            int idx = tid + j * 256;
            int r = idx >> 4, fg = idx & 15;
            float4 k = *(const float4*)(Kb + (size_t)(s0 + r) * HD + fg * 4);
            int o = r * SV + fg * 2;
            smu[KHOF + o]     = packbf(k.x, k.y);
            smu[KHOF + o + 1] = packbf(k.z, k.w);
            smu[KLOF + o]     = packbf(flo(k.x), flo(k.y));
            smu[KLOF + o + 1] = packbf(flo(k.z), flo(k.w));
        }
        #pragma unroll
        for (int j = 0; j < 4; j++) {
            int key = j * 16 + 2 * wid + (lane >> 4);
            int kp  = j * 8 + wid;
            #pragma unroll
            for (int s = 0; s < 4; s++) {
                int d = (lane & 15) + s * 16;
                float v  = Vb[(size_t)(s0 + key) * HD + d];
                float pv = __shfl_xor_sync(0xffffffffu, v, 16);
                float ev = (lane < 16) ? v : pv;
                float ov = (lane < 16) ? pv : v;
                if (lane < 16)
                    smu[VHOF + d * SV + kp] = packbf(ev, ov);
                else
                    smu[VLOF + d * SV + kp] = packbf(flo(ev), flo(ov));
            }
        }
        __syncthreads();

        if (s0 <= rowbase + 15) {
            float sacc[8][4];
            #pragma unroll
            for (int nt = 0; nt < 8; nt++)
                #pragma unroll
                for (int e = 0; e < 4; e++) sacc[nt][e] = 0.f;

            #pragma unroll
            for (int ks = 0; ks < 4; ks++) {
                int ab = (wid * 16 + qr) * SV + ks * 8 + qc;
                uint32_t ah[4], al[4];
                ah[0] = smu[QHOF + ab];           ah[1] = smu[QHOF + ab + 8 * SV];
                ah[2] = smu[QHOF + ab + 4];       ah[3] = smu[QHOF + ab + 8 * SV + 4];
                al[0] = smu[QLOF + ab];           al[1] = smu[QLOF + ab + 8 * SV];
                al[2] = smu[QLOF + ab + 4];       al[3] = smu[QLOF + ab + 8 * SV + 4];
                #pragma unroll
                for (int nt = 0; nt < 8; nt++) {
                    int bb = (nt * 8 + qr) * SV + ks * 8 + qc;
                    uint32_t kh0 = smu[KHOF + bb], kh1 = smu[KHOF + bb + 4];
                    uint32_t kl0 = smu[KLOF + bb], kl1 = smu[KLOF + bb + 4];
                    mma16816(sacc[nt], ah, kh0, kh1);
                    mma16816(sacc[nt], ah, kl0, kl1);
                    mma16816(sacc[nt], al, kh0, kh1);
                }
            }

            if (s0 + 63 > rowbase) {
                int rA = rowbase + qr, rB = rA + 8;
                #pragma unroll
                for (int nt = 0; nt < 8; nt++) {
                    int c0 = s0 + nt * 8 + qc * 2;
                    if (c0 > rA)     sacc[nt][0] = -1e30f;
                    if (c0 + 1 > rA) sacc[nt][1] = -1e30f;
                    if (c0 > rB)     sacc[nt][2] = -1e30f;
                    if (c0 + 1 > rB) sacc[nt][3] = -1e30f;
                }
            }

            float mxA = -1e30f, mxB = -1e30f;
            #pragma unroll
            for (int nt = 0; nt < 8; nt++) {
                mxA = fmaxf(mxA, fmaxf(sacc[nt][0], sacc[nt][1]));
                mxB = fmaxf(mxB, fmaxf(sacc[nt][2], sacc[nt][3]));
            }
            mxA = fmaxf(mxA, __shfl_xor_sync(0xffffffffu, mxA, 1));
            mxA = fmaxf(mxA, __shfl_xor_sync(0xffffffffu, mxA, 2));
            mxB = fmaxf(mxB, __shfl_xor_sync(0xffffffffu, mxB, 1));
            mxB = fmaxf(mxB, __shfl_xor_sync(0xffffffffu, mxB, 2));
            mxA *= 0.125f; mxB *= 0.125f;

            float mnA = fmaxf(mr[0], mxA), mnB = fmaxf(mr[1], mxB);
            float corrA = fexp2((mr[0] - mnA) * 1.44269504f);
            float corrB = fexp2((mr[1] - mnB) * 1.44269504f);
            mr[0] = mnA; mr[1] = mnB;
            float nbA = mnA * 1.44269504f, nbB = mnB * 1.44269504f;

            const float C1 = 0.125f * 1.44269504f;
            float suA = 0.f, suB = 0.f;
            #pragma unroll
            for (int nt = 0; nt < 8; nt++) {
                float p0 = fexp2(fmaf(sacc[nt][0], C1, -nbA));
                float p1 = fexp2(fmaf(sacc[nt][1], C1, -nbA));
                float p2 = fexp2(fmaf(sacc[nt][2], C1, -nbB));
                float p3 = fexp2(fmaf(sacc[nt][3], C1, -nbB));
                sacc[nt][0] = p0; sacc[nt][1] = p1;
                sacc[nt][2] = p2; sacc[nt][3] = p3;
                suA += p0 + p1; suB += p2 + p3;
            }
            suA += __shfl_xor_sync(0xffffffffu, suA, 1);
            suA += __shfl_xor_sync(0xffffffffu, suA, 2);
            suB += __shfl_xor_sync(0xffffffffu, suB, 1);
            suB += __shfl_xor_sync(0xffffffffu, suB, 2);
            lr[0] = lr[0] * corrA + suA;
            lr[1] = lr[1] * corrB + suB;
            #pragma unroll
            for (int nt = 0; nt < 8; nt++) {
                oacc[nt][0] *= corrA; oacc[nt][1] *= corrA;
                oacc[nt][2] *= corrB; oacc[nt][3] *= corrB;
            }

            uint32_t ph[4][4], pl[4][4];
            #pragma unroll
            for (int kk = 0; kk < 4; kk++) {
                float a0 = sacc[2*kk][0],   a1 = sacc[2*kk][1];
                float a2 = sacc[2*kk][2],   a3 = sacc[2*kk][3];
                float b0 = sacc[2*kk+1][0], b1 = sacc[2*kk+1][1];
                float b2 = sacc[2*kk+1][2], b3 = sacc[2*kk+1][3];
                ph[kk][0] = packbf(a0, a1); ph[kk][1] = packbf(a2, a3);
                ph[kk][2] = packbf(b0, b1); ph[kk][3] = packbf(b2, b3);
                pl[kk][0] = packbf(flo(a0), flo(a1)); pl[kk][1] = packbf(flo(a2), flo(a3));
                pl[kk][2] = packbf(flo(b0), flo(b1)); pl[kk][3] = packbf(flo(b2), flo(b3));
            }

            #pragma unroll
            for (int nt = 0; nt < 8; nt++) {
                #pragma unroll
                for (int kk = 0; kk < 4; kk++) {
                    int vb = (nt * 8 + qr) * SV + kk * 8 + qc;
                    uint32_t vh0 = smu[VHOF + vb], vh1 = smu[VHOF + vb + 4];
                    uint32_t vl0 = smu[VLOF + vb], vl1 = smu[VLOF + vb + 4];
                    mma16816(oacc[nt], ph[kk], vh0, vh1);
                    mma16816(oacc[nt], ph[kk], vl0, vl1);
                    mma16816(oacc[nt], pl[kk], vh0, vh1);
                }
            }
        }
    }

    float ivA = 1.0f / lr[0], ivB = 1.0f / lr[1];
    int b = bh >> 4, h = bh & 15;
    int rA = rowbase + qr, rB = rA + 8;
    #pragma unroll
    for (int nt = 0; nt < 8; nt++) {
        int d = nt * 8 + qc * 2;
        *(float2*)&g_att[((size_t)(b * SEQ + rA)) * DIMC + h * HD + d] =
            make_float2(oacc[nt][0] * ivA, oacc[nt][1] * ivA);
        *(float2*)&g_att[((size_t)(b * SEQ + rB)) * DIMC + h * HD + d] =
            make_float2(oacc[nt][2] * ivB, oacc[nt][3] * ivB);
    }
}

// ---------------- launch ----------------
extern "C" void kernel_launch(void* const* d_in, const int* in_sizes, int n_in,
                              void* d_out, int out_size)
{
    const float* query = (const float*)d_in[0];
    const float* key   = (const float*)d_in[1];
    const float* value = (const float*)d_in[2];
    const float* Wq = (const float*)d_in[3];
    const float* bq = (const float*)d_in[4];
    const float* Wk = (const float*)d_in[5];
    const float* bk = (const float*)d_in[6];
    const float* Wv = (const float*)d_in[7];
    const float* bv = (const float*)d_in[8];
    const float* Wo = (const float*)d_in[9];
    const float* bo = (const float*)d_in[10];
    float* out = (float*)d_out;

    cudaFuncSetAttribute(pgemm_kernel<0>, cudaFuncAttributeMaxDynamicSharedMemorySize, GSMEM_BYTES);
    cudaFuncSetAttribute(pgemm_kernel<1>, cudaFuncAttributeMaxDynamicSharedMemorySize, GSMEM_BYTES);
    cudaFuncSetAttribute(attn_kernel, cudaFuncAttributeMaxDynamicSharedMemorySize, ATT_SMEM_BYTES);

    int n4 = BT * DIMC / 4;

    rope_table_kernel<<<SEQ * 32 / 256, 256>>>();
    asplit3_kernel<<<dim3(n4 / 256, 3), 256>>>((const float4*)query,
                                               (const float4*)key,
                                               (const float4*)value);
    wsplit4_kernel<<<dim3(32, 32, 4), dim3(32, 8)>>>(Wq, Wk, Wv, Wo);

    pgemm_kernel<0><<<dim3(8, 64, 3), 256, GSMEM_BYTES>>>(bq, bk, bv, nullptr);

    attn_kernel<<<dim3(SEQ / 128, BATCH * NH), 256, ATT_SMEM_BYTES>>>();

    asplit_att_kernel<<<n4 / 256, 256>>>();
    pgemm_kernel<1><<<dim3(8, 64, 1), 256, GSMEM_BYTES>>>(bo, nullptr, nullptr, out);
}

// round 8
// speedup vs baseline: 3.0083x; 1.0296x over previous
#include <cuda_runtime.h>
#include <cuda_bf16.h>
#include <math.h>
#include <stdint.h>

#define DIMC 1024
#define NH 16
#define HD 64
#define BATCH 4
#define SEQ 2048
#define BT (BATCH*SEQ)
#define MK ((size_t)BT*DIMC)     // 8M elements

// ---------------- scratch (allocation-free) ----------------
__device__ float g_q[(size_t)BATCH*NH*SEQ*HD];
__device__ float g_k[(size_t)BATCH*NH*SEQ*HD];
__device__ float g_v[(size_t)BATCH*NH*SEQ*HD];
__device__ __nv_bfloat16 g_ahi[3*MK];                  // slots: 0=q/att, 1=k, 2=v
__device__ __nv_bfloat16 g_alo[3*MK];
__device__ __nv_bfloat16 g_whi[4*(size_t)DIMC*DIMC];   // slots: q,k,v,o  [N,K]
__device__ __nv_bfloat16 g_wlo[4*(size_t)DIMC*DIMC];
__device__ float2 g_rope[SEQ*32];                      // (cos,sin) per (t, d/2)

// ---------------- PTX helpers (sm_80+ features only; compute_103-safe) ----------------
__device__ __forceinline__ uint32_t smem_u32(const void* p) {
    uint32_t a;
    asm("{ .reg .u64 t; cvta.to.shared.u64 t, %1; cvt.u32.u64 %0, t; }" : "=r"(a) : "l"(p));
    return a;
}
__device__ __forceinline__ void cpasync16(uint32_t saddr, const void* g) {
    asm volatile("cp.async.cg.shared.global [%0], [%1], 16;" :: "r"(saddr), "l"(g));
}
__device__ __forceinline__ void ldsm4(uint32_t* r, uint32_t addr) {
    asm volatile("ldmatrix.sync.aligned.m8n8.x4.shared.b16 {%0,%1,%2,%3}, [%4];"
                 : "=r"(r[0]), "=r"(r[1]), "=r"(r[2]), "=r"(r[3]) : "r"(addr));
}
__device__ __forceinline__ void mma16816(float* d, const uint32_t* a, uint32_t b0, uint32_t b1) {
    asm volatile("mma.sync.aligned.m16n8k16.row.col.f32.bf16.bf16.f32 "
                 "{%0,%1,%2,%3}, {%4,%5,%6,%7}, {%8,%9}, {%0,%1,%2,%3};"
                 : "+f"(d[0]), "+f"(d[1]), "+f"(d[2]), "+f"(d[3])
                 : "r"(a[0]), "r"(a[1]), "r"(a[2]), "r"(a[3]), "r"(b0), "r"(b1));
}
__device__ __forceinline__ uint32_t packbf(float a, float b) {
    __nv_bfloat162 t = __floats2bfloat162_rn(a, b);
    return *(uint32_t*)&t;
}
__device__ __forceinline__ float flo(float x) {
    return x - __bfloat162float(__float2bfloat16(x));
}
// exp2 on the FMA/ALU pipes only (no MUFU); input <= ~0, clamped at -30.
__device__ __forceinline__ float fexp2(float t) {
    t = fmaxf(t, -30.0f);
    float r = t + 12582912.0f;
    int n = __float_as_int(r) - 0x4B400000;
    float f = t - (r - 12582912.0f);
    float p = 1.3333558146e-3f;
    p = fmaf(p, f, 9.6181291077e-3f);
    p = fmaf(p, f, 5.5504108664e-2f);
    p = fmaf(p, f, 2.4022650696e-1f);
    p = fmaf(p, f, 6.9314718056e-1f);
    p = fmaf(p, f, 1.0f);
    return __int_as_float(__float_as_int(p) + (n << 23));
}

// ---------------- helper kernels ----------------
__global__ __launch_bounds__(256) void rope_table_kernel() {
    int idx = blockIdx.x * 256 + threadIdx.x;
    int t = idx >> 5, f = idx & 31;
    double invf = 1.0 / pow(10000.0, (double)(2 * f) / 64.0);
    float ang = (float)t * (float)invf;
    g_rope[idx] = make_float2((float)cos((double)ang), (float)sin((double)ang));
}

// split q/k/v inputs into bf16 hi/lo, slots 0/1/2 (z = blockIdx.y)
__global__ __launch_bounds__(256) void asplit3_kernel(const float4* __restrict__ q,
                                                      const float4* __restrict__ k,
                                                      const float4* __restrict__ v) {
    int z = blockIdx.y;
    const float4* src = (z == 0) ? q : (z == 1) ? k : v;
    size_t i = blockIdx.x * 256 + threadIdx.x;
    float4 val = src[i];
    float vv[4] = {val.x, val.y, val.z, val.w};
    __nv_bfloat16 h[4], l[4];
    #pragma unroll
    for (int j = 0; j < 4; j++) {
        h[j] = __float2bfloat16(vv[j]);
        l[j] = __float2bfloat16(vv[j] - __bfloat162float(h[j]));
    }
    size_t o = z * MK + 4 * i;
    *(uint2*)(g_ahi + o) = *(uint2*)h;
    *(uint2*)(g_alo + o) = *(uint2*)l;
}

// W [K,N] fp32 -> transposed (hi,lo) bf16 [N,K], slot z
__global__ __launch_bounds__(256) void wsplit4_kernel(const float* __restrict__ Wq,
                                                      const float* __restrict__ Wk,
                                                      const float* __restrict__ Wv,
                                                      const float* __restrict__ Wo) {
    __shared__ float tile[32][33];
    int z = blockIdx.z;
    const float* W = (z == 0) ? Wq : (z == 1) ? Wk : (z == 2) ? Wv : Wo;
    size_t wof = (size_t)z * DIMC * DIMC;
    int n0 = blockIdx.x * 32, k0 = blockIdx.y * 32;
    int x = threadIdx.x, y0 = threadIdx.y;
    for (int j = y0; j < 32; j += 8)
        tile[j][x] = W[(size_t)(k0 + j) * DIMC + n0 + x];
    __syncthreads();
    for (int j = y0; j < 32; j += 8) {
        float v = tile[x][j];
        __nv_bfloat16 h = __float2bfloat16(v);
        size_t o = wof + (size_t)(n0 + j) * DIMC + k0 + x;
        g_whi[o] = h;
        g_wlo[o] = __float2bfloat16(v - __bfloat162float(h));
    }
}

// ---------------- cp.async double-buffered HMMA GEMM (ldmatrix fragments) ----------------
// C[8192,1024] = A W + b, 3-term bf16 split. CTA 128x128, BK=32, 8 warps.
// MODE 0: fused QKV (blockIdx.z = 0/1/2 -> src slot, W slot, dest, RoPE)
// MODE 1: final projection (A slot 0, W slot 3, writes outp)
#define S32 20                       // u32 stride per smem row (80 bytes)
#define ARR_B (128*S32*4)            // bytes per array (10240)
#define STAGE_B (4*ARR_B)            // bytes per stage (40960)
#define GSMEM_BYTES (2*STAGE_B)      // 81920

template<int MODE>
__global__ __launch_bounds__(256, 2) void pgemm_kernel(const float* __restrict__ b0p,
                                                       const float* __restrict__ b1p,
                                                       const float* __restrict__ b2p,
                                                       float* __restrict__ outp)
{
    extern __shared__ uint32_t smu[];
    const uint32_t su = smem_u32(smu);

    const int tid  = threadIdx.x;
    const int lane = tid & 31;
    const int wid  = tid >> 5;
    const int wm = wid & 1;
    const int wn = wid >> 1;
    const int m0 = blockIdx.y << 7, n0 = blockIdx.x << 7;
    const int z = (MODE == 0) ? blockIdx.z : 3;

    const __nv_bfloat16* ahi = g_ahi + ((MODE == 0) ? (size_t)z * MK : 0) + (size_t)m0 * DIMC;
    const __nv_bfloat16* alo = g_alo + ((MODE == 0) ? (size_t)z * MK : 0) + (size_t)m0 * DIMC;
    const __nv_bfloat16* whi = g_whi + (size_t)z * DIMC * DIMC + (size_t)n0 * DIMC;
    const __nv_bfloat16* wlo = g_wlo + (size_t)z * DIMC * DIMC + (size_t)n0 * DIMC;
    const float* bias = (MODE == 1) ? b0p : (z == 0) ? b0p : (z == 1) ? b1p : b2p;

    const int l_row0 = tid >> 2, l_seg = tid & 3;
    const int l_row1 = l_row0 + 64;

    float acc[4][4][4];
    #pragma unroll
    for (int i = 0; i < 4; i++)
        #pragma unroll
        for (int j = 0; j < 4; j++)
            #pragma unroll
            for (int r = 0; r < 4; r++) acc[i][j][r] = 0.f;

    // ldmatrix lane-address offsets (bytes)
    // A: tiles r0=(rows0-7,k0-7) r1=(rows8-15,k0-7) r2=(rows0-7,k8-15) r3=(rows8-15,k8-15)
    const uint32_t a_loff = (uint32_t)(((lane & 7) + 8 * ((lane >> 3) & 1)) * S32 * 4
                                       + ((lane >> 4) & 1) * 16);
    // B: tiles r0=(n0-7,k0-7) r1=(n0-7,k8-15) r2=(n8-15,k0-7) r3=(n8-15,k8-15)
    const uint32_t b_loff = (uint32_t)(((lane & 7) + 8 * ((lane >> 4) & 1)) * S32 * 4
                                       + ((lane >> 3) & 1) * 16);

    auto issue = [&](int c, int buf) {
        int k0 = c << 5;
        uint32_t base = su + buf * STAGE_B;
        #pragma unroll
        for (int rr = 0; rr < 2; rr++) {
            int row = rr ? l_row1 : l_row0;
            size_t g = (size_t)row * DIMC + k0 + l_seg * 8;
            uint32_t so = (uint32_t)(row * S32 + l_seg * 4) * 4;
            cpasync16(base + 0 * ARR_B + so, ahi + g);
            cpasync16(base + 1 * ARR_B + so, alo + g);
            cpasync16(base + 2 * ARR_B + so, whi + g);
            cpasync16(base + 3 * ARR_B + so, wlo + g);
        }
        asm volatile("cp.async.commit_group;");
    };

    issue(0, 0);
    for (int c = 0; c < 32; c++) {
        int buf = c & 1;
        if (c < 31) {
            issue(c + 1, buf ^ 1);
            asm volatile("cp.async.wait_group 1;");
        } else {
            asm volatile("cp.async.wait_group 0;");
        }
        __syncthreads();

        uint32_t sb = su + buf * STAGE_B;

        #pragma unroll
        for (int ks2 = 0; ks2 < 2; ks2++) {         // two k16 slices
            uint32_t ksb = ks2 * 32;                 // 8 u32 = 32 bytes
            uint32_t ah[4][4], al[4][4], bh[2][4], bl[2][4];
            #pragma unroll
            for (int mt = 0; mt < 4; mt++) {
                uint32_t ab = sb + (uint32_t)((wm * 64 + mt * 16) * S32 * 4) + ksb + a_loff;
                ldsm4(ah[mt], ab);
                ldsm4(al[mt], ab + ARR_B);
            }
            #pragma unroll
            for (int p = 0; p < 2; p++) {            // nt pairs {0,1},{2,3}
                uint32_t bb = sb + 2 * ARR_B + (uint32_t)((wn * 32 + p * 16) * S32 * 4) + ksb + b_loff;
                ldsm4(bh[p], bb);
                ldsm4(bl[p], bb + ARR_B);
            }
            #pragma unroll
            for (int mt = 0; mt < 4; mt++)
                #pragma unroll
                for (int nt = 0; nt < 4; nt++) {
                    int p = nt >> 1, ix = (nt & 1) * 2;
                    mma16816(acc[mt][nt], ah[mt], bh[p][ix], bh[p][ix + 1]);
                    mma16816(acc[mt][nt], ah[mt], bl[p][ix], bl[p][ix + 1]);
                    mma16816(acc[mt][nt], al[mt], bh[p][ix], bh[p][ix + 1]);
                }
        }
        __syncthreads();
    }

    const int quad = lane >> 2, tc = lane & 3;
    #pragma unroll
    for (int mt = 0; mt < 4; mt++) {
        #pragma unroll
        for (int nt = 0; nt < 4; nt++) {
            #pragma unroll
            for (int half = 0; half < 2; half++) {
                int m = m0 + wm * 64 + mt * 16 + quad + half * 8;
                int n = n0 + wn * 32 + nt * 8 + tc * 2;
                float v0 = acc[mt][nt][half * 2]     + bias[n];
                float v1 = acc[mt][nt][half * 2 + 1] + bias[n + 1];
                if (MODE == 0) {
                    float* out = (z == 0) ? g_q : (z == 1) ? g_k : g_v;
                    int b = m >> 11, t = m & (SEQ - 1);
                    int h = n >> 6, d = n & 63;
                    float oe, oo;
                    if (z < 2) {
                        float2 cs = g_rope[t * 32 + (d >> 1)];
                        oe = v0 * cs.x - v1 * cs.y;
                        oo = v0 * cs.y + v1 * cs.x;
                    } else { oe = v0; oo = v1; }
                    size_t base = ((size_t)(b * NH + h) * SEQ + t) * HD + d;
                    out[base]     = oe;
                    out[base + 1] = oo;
                } else {
                    size_t base = (size_t)m * DIMC + n;
                    outp[base]     = v0;
                    outp[base + 1] = v1;
                }
            }
        }
    }
}

// ---------------- tensorized causal flash attention ----------------
// Unchanged compute (proven R6); epilogue now writes bf16 hi/lo split directly
// into g_ahi/g_alo slot 0 (feeds the final projection; no fp32 round-trip).
#define SV 36
#define QHOF 0
#define QLOF 4608
#define KHOF 9216
#define KLOF 11520
#define VHOF 13824
#define VLOF 16128
#define ATT_SMEM_BYTES (18432*4)

__global__ __launch_bounds__(256) void attn_kernel()
{
    extern __shared__ uint32_t smu[];

    const int tid  = threadIdx.x;
    const int lane = tid & 31;
    const int wid  = tid >> 5;
    const int bh   = blockIdx.y;
    const int m0   = ((int)gridDim.x - 1 - (int)blockIdx.x) * 128;

    const float* Qb = g_q + (size_t)bh * SEQ * HD;
    const float* Kb = g_k + (size_t)bh * SEQ * HD;
    const float* Vb = g_v + (size_t)bh * SEQ * HD;

    #pragma unroll
    for (int j = 0; j < 8; j++) {
        int idx = tid + j * 256;
        int r = idx >> 4, fg = idx & 15;
        float4 q = *(const float4*)(Qb + (size_t)(m0 + r) * HD + fg * 4);
        int o = r * SV + fg * 2;
        smu[QHOF + o]     = packbf(q.x, q.y);
        smu[QHOF + o + 1] = packbf(q.z, q.w);
        smu[QLOF + o]     = packbf(flo(q.x), flo(q.y));
        smu[QLOF + o + 1] = packbf(flo(q.z), flo(q.w));
    }

    float oacc[8][4];
    #pragma unroll
    for (int nt = 0; nt < 8; nt++)
        #pragma unroll
        for (int e = 0; e < 4; e++) oacc[nt][e] = 0.f;
    float mr[2] = {-1e30f, -1e30f};
    float lr[2] = {0.f, 0.f};

    const int qr = lane >> 2, qc = lane & 3;
    const int rowbase = m0 + wid * 16;
    const int ntiles = m0 / 64 + 2;

    for (int tix = 0; tix < ntiles; tix++) {
        int s0 = tix * 64;
        __syncthreads();

        #pragma unroll
        for (int j = 0; j < 4; j++) {
            int idx = tid + j * 256;
            int r = idx >> 4, fg = idx & 15;
            float4 k = *(const float4*)(Kb + (size_t)(s0 + r) * HD + fg * 4);
            int o = r * SV + fg * 2;
            smu[KHOF + o]     = packbf(k.x, k.y);
            smu[KHOF + o + 1] = packbf(k.z, k.w);
            smu[KLOF + o]     = packbf(flo(k.x), flo(k.y));
            smu[KLOF + o + 1] = packbf(flo(k.z), flo(k.w));
        }
        #pragma unroll
        for (int j = 0; j < 4; j++) {
            int key = j * 16 + 2 * wid + (lane >> 4);
            int kp  = j * 8 + wid;
            #pragma unroll
            for (int s = 0; s < 4; s++) {
                int d = (lane & 15) + s * 16;
                float v  = Vb[(size_t)(s0 + key) * HD + d];
                float pv = __shfl_xor_sync(0xffffffffu, v, 16);
                float ev = (lane < 16) ? v : pv;
                float ov = (lane < 16) ? pv : v;
                if (lane < 16)
                    smu[VHOF + d * SV + kp] = packbf(ev, ov);
                else
                    smu[VLOF + d * SV + kp] = packbf(flo(ev), flo(ov));
            }
        }
        __syncthreads();

        if (s0 <= rowbase + 15) {
            float sacc[8][4];
            #pragma unroll
            for (int nt = 0; nt < 8; nt++)
                #pragma unroll
                for (int e = 0; e < 4; e++) sacc[nt][e] = 0.f;

            #pragma unroll
            for (int ks = 0; ks < 4; ks++) {
                int ab = (wid * 16 + qr) * SV + ks * 8 + qc;
                uint32_t ah[4], al[4];
                ah[0] = smu[QHOF + ab];           ah[1] = smu[QHOF + ab + 8 * SV];
                ah[2] = smu[QHOF + ab + 4];       ah[3] = smu[QHOF + ab + 8 * SV + 4];
                al[0] = smu[QLOF + ab];           al[1] = smu[QLOF + ab + 8 * SV];
                al[2] = smu[QLOF + ab + 4];       al[3] = smu[QLOF + ab + 8 * SV + 4];
                #pragma unroll
                for (int nt = 0; nt < 8; nt++) {
                    int bb = (nt * 8 + qr) * SV + ks * 8 + qc;
                    uint32_t kh0 = smu[KHOF + bb], kh1 = smu[KHOF + bb + 4];
                    uint32_t kl0 = smu[KLOF + bb], kl1 = smu[KLOF + bb + 4];
                    mma16816(sacc[nt], ah, kh0, kh1);
                    mma16816(sacc[nt], ah, kl0, kl1);
                    mma16816(sacc[nt], al, kh0, kh1);
                }
            }

            if (s0 + 63 > rowbase) {
                int rA = rowbase + qr, rB = rA + 8;
                #pragma unroll
                for (int nt = 0; nt < 8; nt++) {
                    int c0 = s0 + nt * 8 + qc * 2;
                    if (c0 > rA)     sacc[nt][0] = -1e30f;
                    if (c0 + 1 > rA) sacc[nt][1] = -1e30f;
                    if (c0 > rB)     sacc[nt][2] = -1e30f;
                    if (c0 + 1 > rB) sacc[nt][3] = -1e30f;
                }
            }

            float mxA = -1e30f, mxB = -1e30f;
            #pragma unroll
            for (int nt = 0; nt < 8; nt++) {
                mxA = fmaxf(mxA, fmaxf(sacc[nt][0], sacc[nt][1]));
                mxB = fmaxf(mxB, fmaxf(sacc[nt][2], sacc[nt][3]));
            }
            mxA = fmaxf(mxA, __shfl_xor_sync(0xffffffffu, mxA, 1));
            mxA = fmaxf(mxA, __shfl_xor_sync(0xffffffffu, mxA, 2));
            mxB = fmaxf(mxB, __shfl_xor_sync(0xffffffffu, mxB, 1));
            mxB = fmaxf(mxB, __shfl_xor_sync(0xffffffffu, mxB, 2));
            mxA *= 0.125f; mxB *= 0.125f;

            float mnA = fmaxf(mr[0], mxA), mnB = fmaxf(mr[1], mxB);
            float corrA = fexp2((mr[0] - mnA) * 1.44269504f);
            float corrB = fexp2((mr[1] - mnB) * 1.44269504f);
            mr[0] = mnA; mr[1] = mnB;
            float nbA = mnA * 1.44269504f, nbB = mnB * 1.44269504f;

            const float C1 = 0.125f * 1.44269504f;
            float suA = 0.f, suB = 0.f;
            #pragma unroll
            for (int nt = 0; nt < 8; nt++) {
                float p0 = fexp2(fmaf(sacc[nt][0], C1, -nbA));
                float p1 = fexp2(fmaf(sacc[nt][1], C1, -nbA));
                float p2 = fexp2(fmaf(sacc[nt][2], C1, -nbB));
                float p3 = fexp2(fmaf(sacc[nt][3], C1, -nbB));
                sacc[nt][0] = p0; sacc[nt][1] = p1;
                sacc[nt][2] = p2; sacc[nt][3] = p3;
                suA += p0 + p1; suB += p2 + p3;
            }
            suA += __shfl_xor_sync(0xffffffffu, suA, 1);
            suA += __shfl_xor_sync(0xffffffffu, suA, 2);
            suB += __shfl_xor_sync(0xffffffffu, suB, 1);
            suB += __shfl_xor_sync(0xffffffffu, suB, 2);
            lr[0] = lr[0] * corrA + suA;
            lr[1] = lr[1] * corrB + suB;
            #pragma unroll
            for (int nt = 0; nt < 8; nt++) {
                oacc[nt][0] *= corrA; oacc[nt][1] *= corrA;
                oacc[nt][2] *= corrB; oacc[nt][3] *= corrB;
            }

            uint32_t ph[4][4], pl[4][4];
            #pragma unroll
            for (int kk = 0; kk < 4; kk++) {
                float a0 = sacc[2*kk][0],   a1 = sacc[2*kk][1];
                float a2 = sacc[2*kk][2],   a3 = sacc[2*kk][3];
                float b0 = sacc[2*kk+1][0], b1 = sacc[2*kk+1][1];
                float b2 = sacc[2*kk+1][2], b3 = sacc[2*kk+1][3];
                ph[kk][0] = packbf(a0, a1); ph[kk][1] = packbf(a2, a3);
                ph[kk][2] = packbf(b0, b1); ph[kk][3] = packbf(b2, b3);
                pl[kk][0] = packbf(flo(a0), flo(a1)); pl[kk][1] = packbf(flo(a2), flo(a3));
                pl[kk][2] = packbf(flo(b0), flo(b1)); pl[kk][3] = packbf(flo(b2), flo(b3));
            }

            #pragma unroll
            for (int nt = 0; nt < 8; nt++) {
                #pragma unroll
                for (int kk = 0; kk < 4; kk++) {
                    int vb = (nt * 8 + qr) * SV + kk * 8 + qc;
                    uint32_t vh0 = smu[VHOF + vb], vh1 = smu[VHOF + vb + 4];
                    uint32_t vl0 = smu[VLOF + vb], vl1 = smu[VLOF + vb + 4];
                    mma16816(oacc[nt], ph[kk], vh0, vh1);
                    mma16816(oacc[nt], ph[kk], vl0, vl1);
                    mma16816(oacc[nt], pl[kk], vh0, vh1);
                }
            }
        }
    }

    // ---- epilogue: O/l -> bf16 hi/lo split, slot 0 (direct feed to pgemm<1>) ----
    float ivA = 1.0f / lr[0], ivB = 1.0f / lr[1];
    int b = bh >> 4, h = bh & 15;
    int rA = rowbase + qr, rB = rA + 8;
    #pragma unroll
    for (int nt = 0; nt < 8; nt++) {
        int d = nt * 8 + qc * 2;
        size_t iA = ((size_t)(b * SEQ + rA)) * DIMC + h * HD + d;
        size_t iB = ((size_t)(b * SEQ + rB)) * DIMC + h * HD + d;
        float o0 = oacc[nt][0] * ivA, o1 = oacc[nt][1] * ivA;
        float o2 = oacc[nt][2] * ivB, o3 = oacc[nt][3] * ivB;
        *(uint32_t*)(g_ahi + iA) = packbf(o0, o1);
        *(uint32_t*)(g_alo + iA) = packbf(flo(o0), flo(o1));
        *(uint32_t*)(g_ahi + iB) = packbf(o2, o3);
        *(uint32_t*)(g_alo + iB) = packbf(flo(o2), flo(o3));
    }
}

// ---------------- launch ----------------
extern "C" void kernel_launch(void* const* d_in, const int* in_sizes, int n_in,
                              void* d_out, int out_size)
{
    const float* query = (const float*)d_in[0];
    const float* key   = (const float*)d_in[1];
    const float* value = (const float*)d_in[2];
    const float* Wq = (const float*)d_in[3];
    const float* bq = (const float*)d_in[4];
    const float* Wk = (const float*)d_in[5];
    const float* bk = (const float*)d_in[6];
    const float* Wv = (const float*)d_in[7];
    const float* bv = (const float*)d_in[8];
    const float* Wo = (const float*)d_in[9];
    const float* bo = (const float*)d_in[10];
    float* out = (float*)d_out;

    cudaFuncSetAttribute(pgemm_kernel<0>, cudaFuncAttributeMaxDynamicSharedMemorySize, GSMEM_BYTES);
    cudaFuncSetAttribute(pgemm_kernel<1>, cudaFuncAttributeMaxDynamicSharedMemorySize, GSMEM_BYTES);
    cudaFuncSetAttribute(attn_kernel, cudaFuncAttributeMaxDynamicSharedMemorySize, ATT_SMEM_BYTES);

    int n4 = BT * DIMC / 4;

    rope_table_kernel<<<SEQ * 32 / 256, 256>>>();
    asplit3_kernel<<<dim3(n4 / 256, 3), 256>>>((const float4*)query,
                                               (const float4*)key,
                                               (const float4*)value);
    wsplit4_kernel<<<dim3(32, 32, 4), dim3(32, 8)>>>(Wq, Wk, Wv, Wo);

    pgemm_kernel<0><<<dim3(8, 64, 3), 256, GSMEM_BYTES>>>(bq, bk, bv, nullptr);

    attn_kernel<<<dim3(SEQ / 128, BATCH * NH), 256, ATT_SMEM_BYTES>>>();

    pgemm_kernel<1><<<dim3(8, 64, 1), 256, GSMEM_BYTES>>>(bo, nullptr, nullptr, out);
}

// round 9
// speedup vs baseline: 3.3789x; 1.1232x over previous
#include <cuda_runtime.h>
#include <cuda_bf16.h>
#include <math.h>
#include <stdint.h>

#define DIMC 1024
#define NH 16
#define HD 64
#define BATCH 4
#define SEQ 2048
#define BT (BATCH*SEQ)
#define MK ((size_t)BT*DIMC)     // 8M elements
#define BHD ((size_t)BATCH*NH*SEQ*HD)

// ---------------- scratch (allocation-free) ----------------
__device__ float g_v[BHD];                             // fp32 V (pre-transpose)
__device__ __nv_bfloat16 g_qhi[BHD], g_qlo[BHD];       // RoPE'd Q, [B,H,T,D]
__device__ __nv_bfloat16 g_khi[BHD], g_klo[BHD];       // RoPE'd K, [B,H,T,D]
__device__ __nv_bfloat16 g_vthi[BHD], g_vtlo[BHD];     // V^T, [B,H,D,S]
__device__ __nv_bfloat16 g_ahi[3*MK];                  // GEMM A slots: 0=q/att,1=k,2=v
__device__ __nv_bfloat16 g_alo[3*MK];
__device__ __nv_bfloat16 g_whi[4*(size_t)DIMC*DIMC];   // W slots q,k,v,o  [N,K]
__device__ __nv_bfloat16 g_wlo[4*(size_t)DIMC*DIMC];
__device__ float2 g_rope[SEQ*32];

// ---------------- PTX helpers (sm_80+ features only; compute_103-safe) ----------------
__device__ __forceinline__ uint32_t smem_u32(const void* p) {
    uint32_t a;
    asm("{ .reg .u64 t; cvta.to.shared.u64 t, %1; cvt.u32.u64 %0, t; }" : "=r"(a) : "l"(p));
    return a;
}
__device__ __forceinline__ void cpasync16(uint32_t saddr, const void* g) {
    asm volatile("cp.async.cg.shared.global [%0], [%1], 16;" :: "r"(saddr), "l"(g));
}
__device__ __forceinline__ void ldsm4(uint32_t* r, uint32_t addr) {
    asm volatile("ldmatrix.sync.aligned.m8n8.x4.shared.b16 {%0,%1,%2,%3}, [%4];"
                 : "=r"(r[0]), "=r"(r[1]), "=r"(r[2]), "=r"(r[3]) : "r"(addr));
}
__device__ __forceinline__ void mma16816(float* d, const uint32_t* a, uint32_t b0, uint32_t b1) {
    asm volatile("mma.sync.aligned.m16n8k16.row.col.f32.bf16.bf16.f32 "
                 "{%0,%1,%2,%3}, {%4,%5,%6,%7}, {%8,%9}, {%0,%1,%2,%3};"
                 : "+f"(d[0]), "+f"(d[1]), "+f"(d[2]), "+f"(d[3])
                 : "r"(a[0]), "r"(a[1]), "r"(a[2]), "r"(a[3]), "r"(b0), "r"(b1));
}
__device__ __forceinline__ uint32_t packbf(float a, float b) {
    __nv_bfloat162 t = __floats2bfloat162_rn(a, b);
    return *(uint32_t*)&t;
}
__device__ __forceinline__ float flo(float x) {
    return x - __bfloat162float(__float2bfloat16(x));
}
__device__ __forceinline__ float fexp2(float t) {
    t = fmaxf(t, -30.0f);
    float r = t + 12582912.0f;
    int n = __float_as_int(r) - 0x4B400000;
    float f = t - (r - 12582912.0f);
    float p = 1.3333558146e-3f;
    p = fmaf(p, f, 9.6181291077e-3f);
    p = fmaf(p, f, 5.5504108664e-2f);
    p = fmaf(p, f, 2.4022650696e-1f);
    p = fmaf(p, f, 6.9314718056e-1f);
    p = fmaf(p, f, 1.0f);
    return __int_as_float(__float_as_int(p) + (n << 23));
}

// ---------------- helper kernels ----------------
__global__ __launch_bounds__(256) void rope_table_kernel() {
    int idx = blockIdx.x * 256 + threadIdx.x;
    int t = idx >> 5, f = idx & 31;
    double invf = 1.0 / pow(10000.0, (double)(2 * f) / 64.0);
    float ang = (float)t * (float)invf;
    g_rope[idx] = make_float2((float)cos((double)ang), (float)sin((double)ang));
}

__global__ __launch_bounds__(256) void asplit3_kernel(const float4* __restrict__ q,
                                                      const float4* __restrict__ k,
                                                      const float4* __restrict__ v) {
    int z = blockIdx.y;
    const float4* src = (z == 0) ? q : (z == 1) ? k : v;
    size_t i = blockIdx.x * 256 + threadIdx.x;
    float4 val = src[i];
    float vv[4] = {val.x, val.y, val.z, val.w};
    __nv_bfloat16 h[4], l[4];
    #pragma unroll
    for (int j = 0; j < 4; j++) {
        h[j] = __float2bfloat16(vv[j]);
        l[j] = __float2bfloat16(vv[j] - __bfloat162float(h[j]));
    }
    size_t o = z * MK + 4 * i;
    *(uint2*)(g_ahi + o) = *(uint2*)h;
    *(uint2*)(g_alo + o) = *(uint2*)l;
}

__global__ __launch_bounds__(256) void wsplit4_kernel(const float* __restrict__ Wq,
                                                      const float* __restrict__ Wk,
                                                      const float* __restrict__ Wv,
                                                      const float* __restrict__ Wo) {
    __shared__ float tile[32][33];
    int z = blockIdx.z;
    const float* W = (z == 0) ? Wq : (z == 1) ? Wk : (z == 2) ? Wv : Wo;
    size_t wof = (size_t)z * DIMC * DIMC;
    int n0 = blockIdx.x * 32, k0 = blockIdx.y * 32;
    int x = threadIdx.x, y0 = threadIdx.y;
    for (int j = y0; j < 32; j += 8)
        tile[j][x] = W[(size_t)(k0 + j) * DIMC + n0 + x];
    __syncthreads();
    for (int j = y0; j < 32; j += 8) {
        float v = tile[x][j];
        __nv_bfloat16 h = __float2bfloat16(v);
        size_t o = wof + (size_t)(n0 + j) * DIMC + k0 + x;
        g_whi[o] = h;
        g_wlo[o] = __float2bfloat16(v - __bfloat162float(h));
    }
}

// V [B,H,S,D] fp32 -> V^T [B,H,D,S] bf16 hi/lo (one-time)
__global__ __launch_bounds__(256) void vtrans_kernel() {
    __shared__ float tile[64][65];
    int s0 = blockIdx.x * 64;
    int bh = blockIdx.y;
    const float* Vb = g_v + (size_t)bh * SEQ * HD;
    int tid = threadIdx.x;
    #pragma unroll
    for (int j = 0; j < 4; j++) {
        int idx = tid + j * 256;
        int r = idx >> 4, c4 = (idx & 15) << 2;
        float4 v = *(const float4*)(Vb + (size_t)(s0 + r) * HD + c4);
        tile[c4 + 0][r] = v.x; tile[c4 + 1][r] = v.y;
        tile[c4 + 2][r] = v.z; tile[c4 + 3][r] = v.w;
    }
    __syncthreads();
    size_t ob = (size_t)bh * HD * SEQ + s0;
    #pragma unroll
    for (int j = 0; j < 8; j++) {
        int u = tid + j * 256;              // 2048 u32 slots
        int d = u >> 5, sp = u & 31;
        float e = tile[d][2 * sp], o = tile[d][2 * sp + 1];
        *(uint32_t*)(g_vthi + ob + (size_t)d * SEQ + 2 * sp) = packbf(e, o);
        *(uint32_t*)(g_vtlo + ob + (size_t)d * SEQ + 2 * sp) = packbf(flo(e), flo(o));
    }
}

// ---------------- cp.async double-buffered HMMA GEMM (ldmatrix fragments) ----------------
#define S32 20
#define ARR_B (128*S32*4)
#define STAGE_B (4*ARR_B)
#define GSMEM_BYTES (2*STAGE_B)

template<int MODE>
__global__ __launch_bounds__(256, 2) void pgemm_kernel(const float* __restrict__ b0p,
                                                       const float* __restrict__ b1p,
                                                       const float* __restrict__ b2p,
                                                       float* __restrict__ outp)
{
    extern __shared__ uint32_t smu[];
    const uint32_t su = smem_u32(smu);

    const int tid  = threadIdx.x;
    const int lane = tid & 31;
    const int wid  = tid >> 5;
    const int wm = wid & 1;
    const int wn = wid >> 1;
    const int m0 = blockIdx.y << 7, n0 = blockIdx.x << 7;
    const int z = (MODE == 0) ? blockIdx.z : 3;

    const __nv_bfloat16* ahi = g_ahi + ((MODE == 0) ? (size_t)z * MK : 0) + (size_t)m0 * DIMC;
    const __nv_bfloat16* alo = g_alo + ((MODE == 0) ? (size_t)z * MK : 0) + (size_t)m0 * DIMC;
    const __nv_bfloat16* whi = g_whi + (size_t)z * DIMC * DIMC + (size_t)n0 * DIMC;
    const __nv_bfloat16* wlo = g_wlo + (size_t)z * DIMC * DIMC + (size_t)n0 * DIMC;
    const float* bias = (MODE == 1) ? b0p : (z == 0) ? b0p : (z == 1) ? b1p : b2p;

    const int l_row0 = tid >> 2, l_seg = tid & 3;
    const int l_row1 = l_row0 + 64;

    float acc[4][4][4];
    #pragma unroll
    for (int i = 0; i < 4; i++)
        #pragma unroll
        for (int j = 0; j < 4; j++)
            #pragma unroll
            for (int r = 0; r < 4; r++) acc[i][j][r] = 0.f;

    const uint32_t a_loff = (uint32_t)(((lane & 7) + 8 * ((lane >> 3) & 1)) * S32 * 4
                                       + ((lane >> 4) & 1) * 16);
    const uint32_t b_loff = (uint32_t)(((lane & 7) + 8 * ((lane >> 4) & 1)) * S32 * 4
                                       + ((lane >> 3) & 1) * 16);

    auto issue = [&](int c, int buf) {
        int k0 = c << 5;
        uint32_t base = su + buf * STAGE_B;
        #pragma unroll
        for (int rr = 0; rr < 2; rr++) {
            int row = rr ? l_row1 : l_row0;
            size_t g = (size_t)row * DIMC + k0 + l_seg * 8;
            uint32_t so = (uint32_t)(row * S32 + l_seg * 4) * 4;
            cpasync16(base + 0 * ARR_B + so, ahi + g);
            cpasync16(base + 1 * ARR_B + so, alo + g);
            cpasync16(base + 2 * ARR_B + so, whi + g);
            cpasync16(base + 3 * ARR_B + so, wlo + g);
        }
        asm volatile("cp.async.commit_group;");
    };

    issue(0, 0);
    for (int c = 0; c < 32; c++) {
        int buf = c & 1;
        if (c < 31) {
            issue(c + 1, buf ^ 1);
            asm volatile("cp.async.wait_group 1;");
        } else {
            asm volatile("cp.async.wait_group 0;");
        }
        __syncthreads();

        uint32_t sb = su + buf * STAGE_B;

        #pragma unroll
        for (int ks2 = 0; ks2 < 2; ks2++) {
            uint32_t ksb = ks2 * 32;
            uint32_t ah[4][4], al[4][4], bh[2][4], bl[2][4];
            #pragma unroll
            for (int mt = 0; mt < 4; mt++) {
                uint32_t ab = sb + (uint32_t)((wm * 64 + mt * 16) * S32 * 4) + ksb + a_loff;
                ldsm4(ah[mt], ab);
                ldsm4(al[mt], ab + ARR_B);
            }
            #pragma unroll
            for (int p = 0; p < 2; p++) {
                uint32_t bb = sb + 2 * ARR_B + (uint32_t)((wn * 32 + p * 16) * S32 * 4) + ksb + b_loff;
                ldsm4(bh[p], bb);
                ldsm4(bl[p], bb + ARR_B);
            }
            #pragma unroll
            for (int mt = 0; mt < 4; mt++)
                #pragma unroll
                for (int nt = 0; nt < 4; nt++) {
                    int p = nt >> 1, ix = (nt & 1) * 2;
                    mma16816(acc[mt][nt], ah[mt], bh[p][ix], bh[p][ix + 1]);
                    mma16816(acc[mt][nt], ah[mt], bl[p][ix], bl[p][ix + 1]);
                    mma16816(acc[mt][nt], al[mt], bh[p][ix], bh[p][ix + 1]);
                }
        }
        __syncthreads();
    }

    const int quad = lane >> 2, tc = lane & 3;
    #pragma unroll
    for (int mt = 0; mt < 4; mt++) {
        #pragma unroll
        for (int nt = 0; nt < 4; nt++) {
            #pragma unroll
            for (int half = 0; half < 2; half++) {
                int m = m0 + wm * 64 + mt * 16 + quad + half * 8;
                int n = n0 + wn * 32 + nt * 8 + tc * 2;
                float v0 = acc[mt][nt][half * 2]     + bias[n];
                float v1 = acc[mt][nt][half * 2 + 1] + bias[n + 1];
                if (MODE == 0) {
                    int b = m >> 11, t = m & (SEQ - 1);
                    int h = n >> 6, d = n & 63;
                    size_t base = ((size_t)(b * NH + h) * SEQ + t) * HD + d;
                    if (z == 2) {
                        g_v[base]     = v0;
                        g_v[base + 1] = v1;
                    } else {
                        float2 cs = g_rope[t * 32 + (d >> 1)];
                        float oe = v0 * cs.x - v1 * cs.y;
                        float oo = v0 * cs.y + v1 * cs.x;
                        uint32_t hi = packbf(oe, oo);
                        uint32_t lo = packbf(flo(oe), flo(oo));
                        if (z == 0) {
                            *(uint32_t*)(g_qhi + base) = hi;
                            *(uint32_t*)(g_qlo + base) = lo;
                        } else {
                            *(uint32_t*)(g_khi + base) = hi;
                            *(uint32_t*)(g_klo + base) = lo;
                        }
                    }
                } else {
                    size_t base = (size_t)m * DIMC + n;
                    outp[base]     = v0;
                    outp[base + 1] = v1;
                }
            }
        }
    }
}

// ---------------- attention: pre-split operands, cp.async 2-stage, ldmatrix ----------------
// Br=128 (8 warps x 16 rows), Bc=64. Q frags in registers (smem-staged prologue).
// smem: 2 stages x {KH,KL,VH,VL}, each 64 rows x 36 u32 (144B) = 73728 B total.
#define ASV 36
#define AARR (64*ASV)          // u32 per array (2304)
#define ASTG (4*AARR)          // u32 per stage (9216)
#define ATT_SMEM_BYTES (2*ASTG*4)

__global__ __launch_bounds__(256, 2) void attn_kernel()
{
    extern __shared__ uint32_t smu[];
    const uint32_t su = smem_u32(smu);

    const int tid  = threadIdx.x;
    const int lane = tid & 31;
    const int wid  = tid >> 5;
    const int bh   = blockIdx.y;
    const int m0   = ((int)gridDim.x - 1 - (int)blockIdx.x) * 128;

    const size_t bhb = (size_t)bh * SEQ * HD;
    const __nv_bfloat16* Khi = g_khi + bhb;
    const __nv_bfloat16* Klo = g_klo + bhb;
    const __nv_bfloat16* Vthi = g_vthi + bhb;   // [d][s]
    const __nv_bfloat16* Vtlo = g_vtlo + bhb;

    const uint32_t a_loff = (uint32_t)(((lane & 7) + 8 * ((lane >> 3) & 1)) * ASV * 4
                                       + ((lane >> 4) & 1) * 16);
    const uint32_t b_loff = (uint32_t)(((lane & 7) + 8 * ((lane >> 4) & 1)) * ASV * 4
                                       + ((lane >> 3) & 1) * 16);

    // ---- prologue: stage Q tile (hi at u32 0, lo at 4608), extract frags to regs ----
    {
        const __nv_bfloat16* Qhi = g_qhi + bhb + (size_t)m0 * HD;
        const __nv_bfloat16* Qlo = g_qlo + bhb + (size_t)m0 * HD;
        #pragma unroll
        for (int j = 0; j < 4; j++) {
            int idx = tid + j * 256;             // 1024 uint4 per array
            int row = idx >> 3, seg = idx & 7;
            size_t g = (size_t)row * HD + seg * 8;
            int o = row * ASV + seg * 4;
            *(uint4*)(smu + o)        = *(const uint4*)(Qhi + g);
            *(uint4*)(smu + 4608 + o) = *(const uint4*)(Qlo + g);
        }
    }
    __syncthreads();
    uint32_t qh[4][4], ql[4][4];
    #pragma unroll
    for (int ks = 0; ks < 4; ks++) {
        uint32_t ab = su + (uint32_t)(wid * 16 * ASV * 4) + ks * 32 + a_loff;
        ldsm4(qh[ks], ab);
        ldsm4(ql[ks], ab + 4608 * 4);
    }
    __syncthreads();

    float oacc[8][4];
    #pragma unroll
    for (int nt = 0; nt < 8; nt++)
        #pragma unroll
        for (int e = 0; e < 4; e++) oacc[nt][e] = 0.f;
    float mr[2] = {-1e30f, -1e30f};
    float lr[2] = {0.f, 0.f};

    const int qr = lane >> 2, qc = lane & 3;
    const int rowbase = m0 + wid * 16;
    const int ntiles = m0 / 64 + 2;

    const int l_row = tid >> 2, l_seg = tid & 3;

    auto issue = [&](int tix, int buf) {
        int s0 = tix * 64;
        uint32_t base = su + (uint32_t)buf * ASTG * 4;
        #pragma unroll
        for (int ss = 0; ss < 2; ss++) {
            int seg = l_seg + ss * 4;
            uint32_t so = (uint32_t)(l_row * ASV + seg * 4) * 4;
            size_t gk = (size_t)(s0 + l_row) * HD + seg * 8;
            size_t gv = (size_t)l_row * SEQ + s0 + seg * 8;
            cpasync16(base + 0 * AARR * 4 + so, Khi + gk);
            cpasync16(base + 1 * AARR * 4 + so, Klo + gk);
            cpasync16(base + 2 * AARR * 4 + so, Vthi + gv);
            cpasync16(base + 3 * AARR * 4 + so, Vtlo + gv);
        }
        asm volatile("cp.async.commit_group;");
    };

    issue(0, 0);
    for (int tix = 0; tix < ntiles; tix++) {
        int s0 = tix * 64;
        int buf = tix & 1;
        if (tix + 1 < ntiles) {
            issue(tix + 1, buf ^ 1);
            asm volatile("cp.async.wait_group 1;");
        } else {
            asm volatile("cp.async.wait_group 0;");
        }
        __syncthreads();

        if (s0 <= rowbase + 15) {
            uint32_t kvB = su + (uint32_t)buf * ASTG * 4;

            // ---- S = Q K^T ----
            float sacc[8][4];
            #pragma unroll
            for (int nt = 0; nt < 8; nt++)
                #pragma unroll
                for (int e = 0; e < 4; e++) sacc[nt][e] = 0.f;

            #pragma unroll
            for (int ks = 0; ks < 4; ks++) {
                #pragma unroll
                for (int p = 0; p < 4; p++) {
                    uint32_t bb = kvB + (uint32_t)(p * 16 * ASV * 4) + ks * 32 + b_loff;
                    uint32_t bhf[4], blf[4];
                    ldsm4(bhf, bb);
                    ldsm4(blf, bb + AARR * 4);
                    mma16816(sacc[2*p],   qh[ks], bhf[0], bhf[1]);
                    mma16816(sacc[2*p],   qh[ks], blf[0], blf[1]);
                    mma16816(sacc[2*p],   ql[ks], bhf[0], bhf[1]);
                    mma16816(sacc[2*p+1], qh[ks], bhf[2], bhf[3]);
                    mma16816(sacc[2*p+1], qh[ks], blf[2], blf[3]);
                    mma16816(sacc[2*p+1], ql[ks], bhf[2], bhf[3]);
                }
            }

            if (s0 + 63 > rowbase) {
                int rA = rowbase + qr, rB = rA + 8;
                #pragma unroll
                for (int nt = 0; nt < 8; nt++) {
                    int c0 = s0 + nt * 8 + qc * 2;
                    if (c0 > rA)     sacc[nt][0] = -1e30f;
                    if (c0 + 1 > rA) sacc[nt][1] = -1e30f;
                    if (c0 > rB)     sacc[nt][2] = -1e30f;
                    if (c0 + 1 > rB) sacc[nt][3] = -1e30f;
                }
            }

            // ---- online softmax (FFMA-pipe exp2) ----
            float mxA = -1e30f, mxB = -1e30f;
            #pragma unroll
            for (int nt = 0; nt < 8; nt++) {
                mxA = fmaxf(mxA, fmaxf(sacc[nt][0], sacc[nt][1]));
                mxB = fmaxf(mxB, fmaxf(sacc[nt][2], sacc[nt][3]));
            }
            mxA = fmaxf(mxA, __shfl_xor_sync(0xffffffffu, mxA, 1));
            mxA = fmaxf(mxA, __shfl_xor_sync(0xffffffffu, mxA, 2));
            mxB = fmaxf(mxB, __shfl_xor_sync(0xffffffffu, mxB, 1));
            mxB = fmaxf(mxB, __shfl_xor_sync(0xffffffffu, mxB, 2));
            mxA *= 0.125f; mxB *= 0.125f;

            float mnA = fmaxf(mr[0], mxA), mnB = fmaxf(mr[1], mxB);
            float corrA = fexp2((mr[0] - mnA) * 1.44269504f);
            float corrB = fexp2((mr[1] - mnB) * 1.44269504f);
            mr[0] = mnA; mr[1] = mnB;
            float nbA = mnA * 1.44269504f, nbB = mnB * 1.44269504f;

            const float C1 = 0.125f * 1.44269504f;
            float suA = 0.f, suB = 0.f;
            #pragma unroll
            for (int nt = 0; nt < 8; nt++) {
                float p0 = fexp2(fmaf(sacc[nt][0], C1, -nbA));
                float p1 = fexp2(fmaf(sacc[nt][1], C1, -nbA));
                float p2 = fexp2(fmaf(sacc[nt][2], C1, -nbB));
                float p3 = fexp2(fmaf(sacc[nt][3], C1, -nbB));
                sacc[nt][0] = p0; sacc[nt][1] = p1;
                sacc[nt][2] = p2; sacc[nt][3] = p3;
                suA += p0 + p1; suB += p2 + p3;
            }
            suA += __shfl_xor_sync(0xffffffffu, suA, 1);
            suA += __shfl_xor_sync(0xffffffffu, suA, 2);
            suB += __shfl_xor_sync(0xffffffffu, suB, 1);
            suB += __shfl_xor_sync(0xffffffffu, suB, 2);
            lr[0] = lr[0] * corrA + suA;
            lr[1] = lr[1] * corrB + suB;
            #pragma unroll
            for (int nt = 0; nt < 8; nt++) {
                oacc[nt][0] *= corrA; oacc[nt][1] *= corrA;
                oacc[nt][2] *= corrB; oacc[nt][3] *= corrB;
            }

            // ---- P -> bf16 hi/lo A-fragments ----
            uint32_t ph[4][4], pl[4][4];
            #pragma unroll
            for (int kk = 0; kk < 4; kk++) {
                float a0 = sacc[2*kk][0],   a1 = sacc[2*kk][1];
                float a2 = sacc[2*kk][2],   a3 = sacc[2*kk][3];
                float b0 = sacc[2*kk+1][0], b1 = sacc[2*kk+1][1];
                float b2 = sacc[2*kk+1][2], b3 = sacc[2*kk+1][3];
                ph[kk][0] = packbf(a0, a1); ph[kk][1] = packbf(a2, a3);
                ph[kk][2] = packbf(b0, b1); ph[kk][3] = packbf(b2, b3);
                pl[kk][0] = packbf(flo(a0), flo(a1)); pl[kk][1] = packbf(flo(a2), flo(a3));
                pl[kk][2] = packbf(flo(b0), flo(b1)); pl[kk][3] = packbf(flo(b2), flo(b3));
            }

            // ---- O += P V ----
            uint32_t vbB = kvB + 2 * AARR * 4;
            #pragma unroll
            for (int kk = 0; kk < 4; kk++) {
                #pragma unroll
                for (int p = 0; p < 4; p++) {
                    uint32_t vb = vbB + (uint32_t)(p * 16 * ASV * 4) + kk * 32 + b_loff;
                    uint32_t vhf[4], vlf[4];
                    ldsm4(vhf, vb);
                    ldsm4(vlf, vb + AARR * 4);
                    mma16816(oacc[2*p],   ph[kk], vhf[0], vhf[1]);
                    mma16816(oacc[2*p],   ph[kk], vlf[0], vlf[1]);
                    mma16816(oacc[2*p],   pl[kk], vhf[0], vhf[1]);
                    mma16816(oacc[2*p+1], ph[kk], vhf[2], vhf[3]);
                    mma16816(oacc[2*p+1], ph[kk], vlf[2], vlf[3]);
                    mma16816(oacc[2*p+1], pl[kk], vhf[2], vhf[3]);
                }
            }
        }
        __syncthreads();
    }

    // ---- epilogue: O/l -> bf16 hi/lo split, slot 0 (direct feed to pgemm<1>) ----
    float ivA = 1.0f / lr[0], ivB = 1.0f / lr[1];
    int b = bh >> 4, h = bh & 15;
    int rA = rowbase + qr, rB = rA + 8;
    #pragma unroll
    for (int nt = 0; nt < 8; nt++) {
        int d = nt * 8 + qc * 2;
        size_t iA = ((size_t)(b * SEQ + rA)) * DIMC + h * HD + d;
        size_t iB = ((size_t)(b * SEQ + rB)) * DIMC + h * HD + d;
        float o0 = oacc[nt][0] * ivA, o1 = oacc[nt][1] * ivA;
        float o2 = oacc[nt][2] * ivB, o3 = oacc[nt][3] * ivB;
        *(uint32_t*)(g_ahi + iA) = packbf(o0, o1);
        *(uint32_t*)(g_alo + iA) = packbf(flo(o0), flo(o1));
        *(uint32_t*)(g_ahi + iB) = packbf(o2, o3);
        *(uint32_t*)(g_alo + iB) = packbf(flo(o2), flo(o3));
    }
}

// ---------------- launch ----------------
extern "C" void kernel_launch(void* const* d_in, const int* in_sizes, int n_in,
                              void* d_out, int out_size)
{
    const float* query = (const float*)d_in[0];
    const float* key   = (const float*)d_in[1];
    const float* value = (const float*)d_in[2];
    const float* Wq = (const float*)d_in[3];
    const float* bq = (const float*)d_in[4];
    const float* Wk = (const float*)d_in[5];
    const float* bk = (const float*)d_in[6];
    const float* Wv = (const float*)d_in[7];
    const float* bv = (const float*)d_in[8];
    const float* Wo = (const float*)d_in[9];
    const float* bo = (const float*)d_in[10];
    float* out = (float*)d_out;

    cudaFuncSetAttribute(pgemm_kernel<0>, cudaFuncAttributeMaxDynamicSharedMemorySize, GSMEM_BYTES);
    cudaFuncSetAttribute(pgemm_kernel<1>, cudaFuncAttributeMaxDynamicSharedMemorySize, GSMEM_BYTES);
    cudaFuncSetAttribute(attn_kernel, cudaFuncAttributeMaxDynamicSharedMemorySize, ATT_SMEM_BYTES);

    int n4 = BT * DIMC / 4;

    rope_table_kernel<<<SEQ * 32 / 256, 256>>>();
    asplit3_kernel<<<dim3(n4 / 256, 3), 256>>>((const float4*)query,
                                               (const float4*)key,
                                               (const float4*)value);
    wsplit4_kernel<<<dim3(32, 32, 4), dim3(32, 8)>>>(Wq, Wk, Wv, Wo);

    pgemm_kernel<0><<<dim3(8, 64, 3), 256, GSMEM_BYTES>>>(bq, bk, bv, nullptr);

    vtrans_kernel<<<dim3(SEQ / 64, BATCH * NH), 256>>>();

    attn_kernel<<<dim3(SEQ / 128, BATCH * NH), 256, ATT_SMEM_BYTES>>>();

    pgemm_kernel<1><<<dim3(8, 64, 1), 256, GSMEM_BYTES>>>(bo, nullptr, nullptr, out);
}